// round 6
// baseline (speedup 1.0000x reference)
#include <cuda_runtime.h>
#include <math.h>

#define B 16
#define I_IN 256
#define H 512
#define O_OUT 256
#define A 1024
#define M 64
#define R 4
#define IFW 471
#define N4H 2048
#define NCOLS3 (IFW + O_OUT)   // 727

// interface offsets
#define OFF_KR     0
#define OFF_BETAR  256
#define OFF_KW     260
#define OFF_BETAW  324
#define OFF_ERASE  325
#define OFF_WRITEV 389
#define OFF_FREE   453
#define OFF_GA     457
#define OFF_GW     458
#define OFF_PI     459

// k57 dynamic smem: 2 tile buffers (64KB each) + pack (32KB) + partials (16KB)
#define SMEM_TILE0 0
#define SMEM_TILE1 65536
#define SMEM_PACK  131072
#define SMEM_PART  163840
#define SMEM_DYN   180224

// ----------------- device scratch -----------------
__device__ float  g_zpart[16][B][N4H];
__device__ float  g_h[B][H];
__device__ float  g_iface[B][IFW];
__device__ float  g_outhid[B][O_OUT];
__device__ float  g_usage[B][A];
__device__ int    g_rank[B][A];
__device__ float  g_cwlog[B][A];
__device__ float  g_ww[B][A];
__device__ float  g_S[B][R];
__device__ float  g_T[B][R];
__device__ float  g_mem[B][A][M];
__device__ float  g_cr[B][R][A];
__device__ double g_PQ[B][R][A];        // packed (p,q)
__device__ double g_UVp[8][B][R][A];    // packed (u,v) partials per stripe

__device__ __forceinline__ float sigf(float x) { return 1.f / (1.f + __expf(-x)); }
__device__ __forceinline__ float oneplusf(float x) {
    return 1.f + (x > 20.f ? x : log1pf(__expf(x)));
}

// packed f32x2 helpers (double as bit-carrier)
__device__ __forceinline__ double pack2(float lo, float hi) {
    double d; asm("mov.b64 %0, {%1,%2};" : "=d"(d) : "f"(lo), "f"(hi)); return d;
}
__device__ __forceinline__ double splat2(float v) {
    double d; asm("mov.b64 %0, {%1,%1};" : "=d"(d) : "f"(v)); return d;
}
__device__ __forceinline__ void fma2(double& acc, double a, double b) {
    asm("fma.rn.f32x2 %0, %1, %2, %3;" : "=d"(acc) : "d"(a), "d"(b), "d"(acc));
}
__device__ __forceinline__ double add2(double a, double b) {
    double d; asm("add.rn.f32x2 %0, %1, %2;" : "=d"(d) : "d"(a), "d"(b)); return d;
}
__device__ __forceinline__ float2 unpack2(double d) {
    float2 f; asm("mov.b64 {%0,%1}, %2;" : "=f"(f.x), "=f"(f.y) : "l"(__double_as_longlong(d))); return f;
}

__device__ __forceinline__ void cpasync16(void* sptr, const void* gptr) {
    unsigned sa = (unsigned)__cvta_generic_to_shared(sptr);
    asm volatile("cp.async.ca.shared.global [%0], [%1], 16;" :: "r"(sa), "l"(gptr) : "memory");
}
__device__ __forceinline__ void cpcommit() {
    asm volatile("cp.async.commit_group;" ::: "memory");
}
template <int N>
__device__ __forceinline__ void cpwait() {
    asm volatile("cp.async.wait_group %0;" :: "n"(N) : "memory");
}

template <int NT>
__device__ __forceinline__ float blockSum(float v, float* s_red) {
    int lane = threadIdx.x & 31, w = threadIdx.x >> 5;
#pragma unroll
    for (int o = 16; o; o >>= 1) v += __shfl_down_sync(0xffffffffu, v, o);
    if (lane == 0) s_red[w] = v;
    __syncthreads();
    if (w == 0) {
        float x = (lane < NT / 32) ? s_red[lane] : 0.f;
#pragma unroll
        for (int o = 16; o; o >>= 1) x += __shfl_down_sync(0xffffffffu, x, o);
        if (lane == 0) s_red[0] = x;
    }
    __syncthreads();
    float res = s_red[0];
    __syncthreads();
    return res;
}
template <int NT>
__device__ __forceinline__ float blockMax(float v, float* s_red) {
    int lane = threadIdx.x & 31, w = threadIdx.x >> 5;
#pragma unroll
    for (int o = 16; o; o >>= 1) v = fmaxf(v, __shfl_down_sync(0xffffffffu, v, o));
    if (lane == 0) s_red[w] = v;
    __syncthreads();
    if (w == 0) {
        float x = (lane < NT / 32) ? s_red[lane] : -1e30f;
#pragma unroll
        for (int o = 16; o; o >>= 1) x = fmaxf(x, __shfl_down_sync(0xffffffffu, x, o));
        if (lane == 0) s_red[0] = x;
    }
    __syncthreads();
    float res = s_red[0];
    __syncthreads();
    return res;
}

// ============ K1: z GEMM, k-split 16 chunks of 64, packed f32x2 ============
__global__ void __launch_bounds__(256, 1)
k1_zpart(const float* __restrict__ x, const float* __restrict__ h_prev,
         const float* __restrict__ rv_prev, const float* __restrict__ Wx,
         const float* __restrict__ Wh) {
    __shared__ double s_in2[B][64];
    int tid = threadIdx.x;
    int ntile = blockIdx.x;
    int kc = blockIdx.y;
    int kbase = kc * 64;
    for (int idx = tid; idx < B * 64; idx += 256) {
        int b = idx >> 6, kl = idx & 63;
        int kk = kbase + kl;
        float v;
        if (kk < 256) v = x[b * I_IN + kk];
        else if (kk < 512) v = rv_prev[b * 256 + (kk - 256)];
        else v = h_prev[b * H + (kk - 512)];
        s_in2[b][kl] = splat2(v);
    }
    __syncthreads();
    int n0 = ntile * 512 + tid * 2;
    const float* Wbase = (kbase < 512) ? (Wx + (size_t)kbase * N4H)
                                       : (Wh + (size_t)(kbase - 512) * N4H);
    const char* Wp = (const char*)(Wbase + n0);
    double acc2[B];
#pragma unroll
    for (int b = 0; b < B; b++) acc2[b] = 0.0;
#pragma unroll 4
    for (int kl = 0; kl < 64; kl++) {
        double w2 = *(const double*)(Wp + (size_t)kl * (N4H * 4));
#pragma unroll
        for (int b = 0; b < B; b++) fma2(acc2[b], s_in2[b][kl], w2);
    }
#pragma unroll
    for (int b = 0; b < B; b++)
        *(double*)&g_zpart[kc][b][n0] = acc2[b];
}

// ============ K2: reduce z partials + LSTM ============
__global__ void __launch_bounds__(512, 1)
k2_lstm(const float* __restrict__ c_prev, const float* __restrict__ b_lstm) {
    int idx = blockIdx.x * 512 + threadIdx.x;
    int b = idx >> 9, hh = idx & 511;
    float zv[4];
#pragma unroll
    for (int g = 0; g < 4; g++) {
        int n = g * H + hh;
        float s = b_lstm[n];
#pragma unroll
        for (int kc = 0; kc < 16; kc++) s += g_zpart[kc][b][n];
        zv[g] = s;
    }
    float c = sigf(zv[1]) * c_prev[idx] + sigf(zv[0]) * tanhf(zv[2]);
    g_h[b][hh] = sigf(zv[3]) * tanhf(c);
}

// ============ K3: iface + out_hidden GEMM, full K ============
__global__ void __launch_bounds__(256, 1)
k3_iface(const float* __restrict__ W_if, const float* __restrict__ W_hid,
         const float* __restrict__ b_if, const float* __restrict__ b_hid) {
    int idx = blockIdx.x * 256 + threadIdx.x;
    if (idx >= B * NCOLS3) return;
    int col = idx % NCOLS3, b = idx / NCOLS3;
    const float* hrow = g_h[b];
    float acc = 0.f;
    if (col < IFW) {
        const float* W = W_if + col;
#pragma unroll 8
        for (int k = 0; k < H; k++) acc = fmaf(hrow[k], W[(size_t)k * IFW], acc);
        g_iface[b][col] = acc + b_if[col];
    } else {
        int c2 = col - IFW;
        const float* W = W_hid + c2;
#pragma unroll 8
        for (int k = 0; k < H; k++) acc = fmaf(hrow[k], W[(size_t)k * O_OUT], acc);
        g_outhid[b][c2] = acc + b_hid[c2];
    }
}

// ============ K4b: usage + rank (stable argsort via counting) + cwlog ============
// grid (8 chunks, B), 256 threads
__global__ void __launch_bounds__(256, 1)
k4b_rank(const float* __restrict__ rw_prev, const float* __restrict__ ww_prev,
         const float* __restrict__ usage_prev, const float* __restrict__ mem_prev) {
    __shared__ float s_u[A];
    __shared__ float s_kw[M];
    __shared__ float s_free[R];
    __shared__ float s_bw[1];
    int tid = threadIdx.x;
    int chunk = blockIdx.x, b = blockIdx.y;

    if (tid < R) s_free[tid] = sigf(g_iface[b][OFF_FREE + tid]);
    if (tid < M) s_kw[tid] = g_iface[b][OFF_KW + tid];
    if (tid == 0) s_bw[0] = oneplusf(g_iface[b][OFF_BETAW]);
    __syncthreads();

    // usage for all A (redundant per chunk, cheap)
#pragma unroll
    for (int ii = 0; ii < 4; ii++) {
        int a = tid + ii * 256;
        float psi = 1.f;
#pragma unroll
        for (int r = 0; r < R; r++)
            psi *= (1.f - s_free[r] * rw_prev[(b * R + r) * A + a]);
        float u = usage_prev[b * A + a], w = ww_prev[b * A + a];
        s_u[a] = (u + w - u * w) * psi;
    }
    __syncthreads();
    if (tid < 128) g_usage[b][chunk * 128 + tid] = s_u[chunk * 128 + tid];

    // rank: thread owns a = chunk*128 + (tid>>1), half = tid&1 scans 512 values
    {
        int a = chunk * 128 + (tid >> 1);
        int half = tid & 1;
        float u = s_u[a];
        int cnt = 0;
        const float4* uu = reinterpret_cast<const float4*>(&s_u[half * 512]);
        int base = half * 512;
#pragma unroll 8
        for (int i = 0; i < 128; i++) {
            float4 v = uu[i];
            int ap = base + i * 4;
            cnt += (v.x < u) || (v.x == u && (ap + 0) < a);
            cnt += (v.y < u) || (v.y == u && (ap + 1) < a);
            cnt += (v.z < u) || (v.z == u && (ap + 2) < a);
            cnt += (v.w < u) || (v.w == u && (ap + 3) < a);
        }
        cnt += __shfl_xor_sync(0xffffffffu, cnt, 1);
        if (half == 0) g_rank[b][a] = cnt;
    }

    // cwlog for own 128 rows (2 threads per row)
    {
        int row = chunk * 128 + (tid >> 1);
        int half = tid & 1;
        const float4* mrow =
            reinterpret_cast<const float4*>(mem_prev + ((size_t)(b * A + row)) * M) + half * 8;
        float d = 0.f, n = 0.f;
#pragma unroll
        for (int q = 0; q < 8; q++) {
            float4 v = mrow[q];
            int m0 = half * 32 + q * 4;
            d += v.x * s_kw[m0] + v.y * s_kw[m0 + 1] + v.z * s_kw[m0 + 2] + v.w * s_kw[m0 + 3];
            n += v.x * v.x + v.y * v.y + v.z * v.z + v.w * v.w;
        }
        d += __shfl_xor_sync(0xffffffffu, d, 1);
        n += __shfl_xor_sync(0xffffffffu, n, 1);
        if (half == 0) {
            float kn2 = 0.f;
#pragma unroll
            for (int m = 0; m < M; m++) { float v = s_kw[m]; kn2 = fmaf(v, v, kn2); }
            g_cwlog[b][row] = s_bw[0] * d / (sqrtf(kn2) * sqrtf(n) + 1e-6f);
        }
    }
}

// ============ K4c: scatter + cumprod + alloc + cw softmax + ww + S,T ============
__global__ void __launch_bounds__(512, 1)
k4c_alloc(const float* __restrict__ rw_prev, const float* __restrict__ prec_prev) {
    int b = blockIdx.x;
    int tid = threadIdx.x;  // 512
    __shared__ float s_sorted[A];
    __shared__ float s_tmp[A];
    __shared__ float s_cw[A];
    __shared__ float s_red[16];
    __shared__ float s_scal[4];

    if (tid == 0) {
        s_scal[0] = sigf(g_iface[b][OFF_GA]);
        s_scal[1] = sigf(g_iface[b][OFF_GW]);
    }

    float u0 = g_usage[b][tid], u1 = g_usage[b][tid + 512];
    int r0 = g_rank[b][tid], r1 = g_rank[b][tid + 512];
    s_sorted[r0] = u0;
    s_sorted[r1] = u1;
    __syncthreads();

    // inclusive cumprod (Hillis-Steele, 10 steps)
    float* src = s_sorted;
    float* dst = s_tmp;
    for (int off = 1; off < A; off <<= 1) {
        for (int i = tid; i < A; i += 512)
            dst[i] = (i >= off) ? src[i - off] * src[i] : src[i];
        __syncthreads();
        float* t = src; src = dst; dst = t;
    }
    // alloc
    float alloc0 = (1.f - u0) * (r0 == 0 ? 1.f : src[r0 - 1]);
    float alloc1 = (1.f - u1) * (r1 == 0 ? 1.f : src[r1 - 1]);

    // c_w softmax
    float l0 = g_cwlog[b][tid], l1 = g_cwlog[b][tid + 512];
    float mx = blockMax<512>(fmaxf(l0, l1), s_red);
    float e0 = __expf(l0 - mx), e1 = __expf(l1 - mx);
    float ssum = blockSum<512>(e0 + e1, s_red);
    float inv = 1.f / ssum;
    s_cw[tid] = e0 * inv;
    s_cw[tid + 512] = e1 * inv;
    __syncthreads();

    float ga = s_scal[0], gw = s_scal[1];
    float sS[R] = {0, 0, 0, 0}, sT[R] = {0, 0, 0, 0};
    float wwv0 = gw * (ga * alloc0 + (1.f - ga) * s_cw[tid]);
    float wwv1 = gw * (ga * alloc1 + (1.f - ga) * s_cw[tid + 512]);
    g_ww[b][tid] = wwv0;
    g_ww[b][tid + 512] = wwv1;
    {
        float pp0 = prec_prev[b * A + tid], pp1 = prec_prev[b * A + tid + 512];
#pragma unroll
        for (int r = 0; r < R; r++) {
            float rw0 = rw_prev[(b * R + r) * A + tid];
            float rw1 = rw_prev[(b * R + r) * A + tid + 512];
            sS[r] = fmaf(pp0, rw0, fmaf(pp1, rw1, sS[r]));
            sT[r] = fmaf(wwv0, rw0, fmaf(wwv1, rw1, sT[r]));
        }
    }
#pragma unroll
    for (int r = 0; r < R; r++) {
        float v = blockSum<512>(sS[r], s_red);
        if (tid == 0) g_S[b][r] = v;
        v = blockSum<512>(sT[r], s_red);
        if (tid == 0) g_T[b][r] = v;
    }
}

// ============ K57: mem write + c_r logits + single-read tiled link pass ============
// grid (8 stripes, B), 512 threads; dynamic smem 180224 B
__global__ void __launch_bounds__(512, 1)
k57_mem_link(const float* __restrict__ mem_prev, const float* __restrict__ link_prev,
             const float* __restrict__ rw_prev) {
    extern __shared__ char dsm[];
    float4* s_tile[2] = {(float4*)(dsm + SMEM_TILE0), (float4*)(dsm + SMEM_TILE1)};
    double* s_pack = (double*)(dsm + SMEM_PACK);
    double* s_part = (double*)(dsm + SMEM_PART);   // [4][128][4] doubles

    __shared__ float s_kr[R][M];
    __shared__ float s_er[M], s_wv[M];
    __shared__ float s_beta[R], s_kn[R];

    int tid = threadIdx.x;                  // 512
    int stripe = blockIdx.x;                // 8 stripes of 128 rows
    int b = blockIdx.y;
    int jbase = stripe * 128;
    const float* Lp = link_prev + (size_t)b * A * A;

    // --- issue tile 0 loads (hide behind pack build + part1) ---
    {
#pragma unroll
        for (int i = 0; i < 8; i++) {
            int idx = tid + i * 512;
            int row = idx >> 5, c4 = idx & 31;
            int slot = row * 32 + (c4 ^ (row & 31));
            cpasync16(&s_tile[0][slot], Lp + (size_t)(jbase + row) * A + c4 * 4);
        }
        cpcommit();
    }

    // --- pack table: s_pack[a*4+r] = (rw, ww*rw) ---
    for (int a = tid; a < A; a += 512) {
        float w = g_ww[b][a];
#pragma unroll
        for (int r = 0; r < R; r++) {
            float rw = rw_prev[(b * R + r) * A + a];
            s_pack[a * 4 + r] = pack2(rw, w * rw);
        }
    }

    // --- params for part1 ---
    if (tid < 256) {
        int r = tid >> 6, m = tid & 63;
        s_kr[r][m] = g_iface[b][OFF_KR + r * M + m];
    } else if (tid < 256 + M) {
        s_er[tid - 256] = sigf(g_iface[b][OFF_ERASE + (tid - 256)]);
    } else if (tid < 256 + 2 * M) {
        s_wv[tid - 256 - M] = g_iface[b][OFF_WRITEV + (tid - 256 - M)];
    }
    __syncthreads();
    if (tid < R) {
        s_beta[tid] = oneplusf(g_iface[b][OFF_BETAR + tid]);
        float s = 0.f;
#pragma unroll
        for (int m = 0; m < M; m++) { float v = s_kr[tid][m]; s = fmaf(v, v, s); }
        s_kn[tid] = sqrtf(s);
    }
    __syncthreads();

    // --- part1: mem update + cr logits for rows [jbase, jbase+128) ---
    {
        int lane16 = tid & 15, m0 = lane16 * 4;
#pragma unroll
        for (int pass = 0; pass < 4; pass++) {
            int a = jbase + pass * 32 + (tid >> 4);
            float w = g_ww[b][a];
            float4 v = *reinterpret_cast<const float4*>(mem_prev + ((size_t)(b * A + a)) * M + m0);
            float n0 = v.x * (1.f - w * s_er[m0])     + w * s_wv[m0];
            float n1 = v.y * (1.f - w * s_er[m0 + 1]) + w * s_wv[m0 + 1];
            float n2 = v.z * (1.f - w * s_er[m0 + 2]) + w * s_wv[m0 + 2];
            float n3 = v.w * (1.f - w * s_er[m0 + 3]) + w * s_wv[m0 + 3];
            *reinterpret_cast<float4*>(&g_mem[b][a][m0]) = make_float4(n0, n1, n2, n3);
            float nn = n0 * n0 + n1 * n1 + n2 * n2 + n3 * n3;
            float d[R];
#pragma unroll
            for (int r = 0; r < R; r++)
                d[r] = n0 * s_kr[r][m0] + n1 * s_kr[r][m0 + 1] +
                       n2 * s_kr[r][m0 + 2] + n3 * s_kr[r][m0 + 3];
#pragma unroll
            for (int o = 8; o; o >>= 1) {
                nn += __shfl_xor_sync(0xffffffffu, nn, o);
#pragma unroll
                for (int r = 0; r < R; r++) d[r] += __shfl_xor_sync(0xffffffffu, d[r], o);
            }
            if (lane16 == 0) {
                float mn = sqrtf(nn);
#pragma unroll
                for (int r = 0; r < R; r++)
                    g_cr[b][r][a] = s_beta[r] * d[r] / (s_kn[r] * mn + 1e-6f);
            }
        }
    }

    // --- tiled link pass ---
    int w = tid >> 5, lane = tid & 31;
    int q = w & 3, cg = w >> 2;       // q: row quarter, cg: col quarter
    int rl = q * 32 + lane;           // owned local row (row pass)
    int ct = cg * 32 + lane;          // owned local col (col pass)

    double pq[4] = {0.0, 0.0, 0.0, 0.0};   // row accumulators, persist across tiles

    for (int t = 0; t < 8; t++) {
        if (t < 7) {
            int nb = (t + 1) & 1;
            int tilebase = (t + 1) * 128;
#pragma unroll
            for (int i = 0; i < 8; i++) {
                int idx = tid + i * 512;
                int row = idx >> 5, c4 = idx & 31;
                int slot = row * 32 + (c4 ^ (row & 31));
                cpasync16(&s_tile[nb][slot], Lp + (size_t)(jbase + row) * A + tilebase + c4 * 4);
            }
            cpcommit();
            cpwait<1>();
        } else {
            cpwait<0>();
        }
        __syncthreads();
        const float4* tile4 = s_tile[t & 1];
        const float* tilef = (const float*)tile4;
        int tilebase = t * 128;

        // col pass: uv for owned col over q's 32 rows
        double uv[4] = {0.0, 0.0, 0.0, 0.0};
        int ct4 = ct >> 2, cti = ct & 3;
#pragma unroll 4
        for (int s = 0; s < 32; s++) {
            int j = q * 32 + s;
            int slot = j * 32 + (ct4 ^ (j & 31));
            float val = tilef[slot * 4 + cti];
            double sv = splat2(val);
            int j4 = (jbase + j) * 4;
            double2 pk01 = *(const double2*)&s_pack[j4];
            double2 pk23 = *(const double2*)&s_pack[j4 + 2];
            fma2(uv[0], sv, pk01.x); fma2(uv[1], sv, pk01.y);
            fma2(uv[2], sv, pk23.x); fma2(uv[3], sv, pk23.y);
        }

        // row pass: pq for owned row over cg's 8 col-groups
#pragma unroll
        for (int s = 0; s < 8; s++) {
            int c4 = cg * 8 + s;
            int slot = rl * 32 + (c4 ^ (rl & 31));
            float4 v = tile4[slot];
            int cb = (tilebase + c4 * 4) * 4;
            {
                double sv = splat2(v.x);
                double2 a0 = *(const double2*)&s_pack[cb];
                double2 a1 = *(const double2*)&s_pack[cb + 2];
                fma2(pq[0], sv, a0.x); fma2(pq[1], sv, a0.y);
                fma2(pq[2], sv, a1.x); fma2(pq[3], sv, a1.y);
            }
            {
                double sv = splat2(v.y);
                double2 a0 = *(const double2*)&s_pack[cb + 4];
                double2 a1 = *(const double2*)&s_pack[cb + 6];
                fma2(pq[0], sv, a0.x); fma2(pq[1], sv, a0.y);
                fma2(pq[2], sv, a1.x); fma2(pq[3], sv, a1.y);
            }
            {
                double sv = splat2(v.z);
                double2 a0 = *(const double2*)&s_pack[cb + 8];
                double2 a1 = *(const double2*)&s_pack[cb + 10];
                fma2(pq[0], sv, a0.x); fma2(pq[1], sv, a0.y);
                fma2(pq[2], sv, a1.x); fma2(pq[3], sv, a1.y);
            }
            {
                double sv = splat2(v.w);
                double2 a0 = *(const double2*)&s_pack[cb + 12];
                double2 a1 = *(const double2*)&s_pack[cb + 14];
                fma2(pq[0], sv, a0.x); fma2(pq[1], sv, a0.y);
                fma2(pq[2], sv, a1.x); fma2(pq[3], sv, a1.y);
            }
        }
        __syncthreads();   // all reads of this tile done (safe to overwrite buffer)

        // flush col partials: s_part[q][ct][r]
#pragma unroll
        for (int r = 0; r < R; r++) s_part[((q * 128) + ct) * 4 + r] = uv[r];
        __syncthreads();
        // reduce 4 row-quarters -> g_UVp
        {
            int ct2 = tid >> 2, r = tid & 3;
            double s = add2(add2(s_part[(0 * 128 + ct2) * 4 + r], s_part[(1 * 128 + ct2) * 4 + r]),
                            add2(s_part[(2 * 128 + ct2) * 4 + r], s_part[(3 * 128 + ct2) * 4 + r]));
            g_UVp[stripe][b][r][tilebase + ct2] = s;
        }
        // next iteration's top __syncthreads covers s_part reuse
    }

    // --- flush row partials: reduce over 4 col-quarters ---
    __syncthreads();
#pragma unroll
    for (int r = 0; r < R; r++) s_part[((cg * 128) + rl) * 4 + r] = pq[r];
    __syncthreads();
    {
        int row2 = tid >> 2, r = tid & 3;
        double s = add2(add2(s_part[(0 * 128 + row2) * 4 + r], s_part[(1 * 128 + row2) * 4 + r]),
                        add2(s_part[(2 * 128 + row2) * 4 + r], s_part[(3 * 128 + row2) * 4 + r]));
        g_PQ[b][r][jbase + row2] = s;
    }
}

// ============ K8: cr softmax + read weights + rv GEMV + output (1 block/b) ====
__global__ void __launch_bounds__(512, 1)
k8_read_out(const float* __restrict__ rw_prev, const float* __restrict__ prec_prev,
            const float* __restrict__ W_rd, const float* __restrict__ b_rd,
            float* __restrict__ out) {
    int b = blockIdx.x;
    int tid = threadIdx.x;  // 512
    __shared__ float s_wr[R][A];
    __shared__ float s_racc[16][R][M];
    __shared__ float s_rv[R * M];
    __shared__ float s_out[2][O_OUT];
    __shared__ float s_pi[R][3];
    __shared__ float s_red[16];

    if (tid < R) {
        float l0 = g_iface[b][OFF_PI + tid * 3 + 0];
        float l1 = g_iface[b][OFF_PI + tid * 3 + 1];
        float l2 = g_iface[b][OFF_PI + tid * 3 + 2];
        float mx = fmaxf(l0, fmaxf(l1, l2));
        float e0 = __expf(l0 - mx), e1 = __expf(l1 - mx), e2 = __expf(l2 - mx);
        float inv = 1.f / (e0 + e1 + e2);
        s_pi[tid][0] = e0 * inv; s_pi[tid][1] = e1 * inv; s_pi[tid][2] = e2 * inv;
    }

#pragma unroll
    for (int r = 0; r < R; r++) {
        float l0 = g_cr[b][r][tid], l1 = g_cr[b][r][tid + 512];
        float mx = blockMax<512>(fmaxf(l0, l1), s_red);
        float e0 = __expf(l0 - mx), e1 = __expf(l1 - mx);
        float s = blockSum<512>(e0 + e1, s_red);
        float inv = 1.f / s;
        s_wr[r][tid] = e0 * inv;
        s_wr[r][tid + 512] = e1 * inv;
    }
    __syncthreads();

    for (int ii = 0; ii < 2; ii++) {
        int a = tid + ii * 512;
        float ww = g_ww[b][a];
        float pp = prec_prev[b * A + a];
#pragma unroll
        for (int r = 0; r < R; r++) {
            float rw = rw_prev[(b * R + r) * A + a];
            float2 PQ = unpack2(g_PQ[b][r][a]);
            double uvs = g_UVp[0][b][r][a];
#pragma unroll
            for (int s8 = 1; s8 < 8; s8++) uvs = add2(uvs, g_UVp[s8][b][r][a]);
            float2 UV = unpack2(uvs);
            float Sr = g_S[b][r], Tr = g_T[b][r];
            float fwd = (1.f - ww) * PQ.x - PQ.y + ww * (Sr - pp * rw);
            float bwd = (1.f - ww) * UV.x - UV.y + pp * (Tr - ww * rw);
            float cr = s_wr[r][a];
            s_wr[r][a] = s_pi[r][0] * bwd + s_pi[r][1] * cr + s_pi[r][2] * fwd;
        }
    }
    __syncthreads();

    {
        int w = tid >> 5, lane = tid & 31;
        float acc[2][R] = {{0, 0, 0, 0}, {0, 0, 0, 0}};
#pragma unroll 4
        for (int i = 0; i < 64; i++) {
            int a = i * 16 + w;
            float m0 = g_mem[b][a][lane];
            float m1 = g_mem[b][a][lane + 32];
#pragma unroll
            for (int r = 0; r < R; r++) {
                float wr = s_wr[r][a];
                acc[0][r] = fmaf(wr, m0, acc[0][r]);
                acc[1][r] = fmaf(wr, m1, acc[1][r]);
            }
        }
#pragma unroll
        for (int r = 0; r < R; r++) {
            s_racc[w][r][lane] = acc[0][r];
            s_racc[w][r][lane + 32] = acc[1][r];
        }
    }
    __syncthreads();
    if (tid < R * M) {
        float s = 0.f;
#pragma unroll
        for (int w = 0; w < 16; w++) s += s_racc[w][tid >> 6][tid & 63];
        s_rv[tid] = s;
    }
    __syncthreads();

    {
        int half = tid >> 8, col = tid & 255;
        float acc = 0.f;
        const float* W = W_rd + (size_t)half * 128 * O_OUT + col;
#pragma unroll 8
        for (int j = 0; j < 128; j++)
            acc = fmaf(s_rv[half * 128 + j], W[(size_t)j * O_OUT], acc);
        s_out[half][col] = acc;
    }
    __syncthreads();
    if (tid < O_OUT) {
        out[b * O_OUT + tid] = s_out[0][tid] + s_out[1][tid] + g_outhid[b][tid] + b_rd[tid];
    }
}

// ----------------- launch -----------------
extern "C" void kernel_launch(void* const* d_in, const int* in_sizes, int n_in,
                              void* d_out, int out_size) {
    (void)in_sizes; (void)n_in; (void)out_size;
    const float* x          = (const float*)d_in[0];
    const float* h_prev     = (const float*)d_in[1];
    const float* c_prev     = (const float*)d_in[2];
    const float* mem_prev   = (const float*)d_in[3];
    const float* rw_prev    = (const float*)d_in[4];
    const float* ww_prev    = (const float*)d_in[5];
    const float* usage_prev = (const float*)d_in[6];
    const float* prec_prev  = (const float*)d_in[7];
    const float* link_prev  = (const float*)d_in[8];
    const float* rv_prev    = (const float*)d_in[9];
    const float* Wx         = (const float*)d_in[10];
    const float* Wh         = (const float*)d_in[11];
    const float* b_lstm     = (const float*)d_in[12];
    const float* W_hid     = (const float*)d_in[13];
    const float* b_hid      = (const float*)d_in[14];
    const float* W_if       = (const float*)d_in[15];
    const float* b_if       = (const float*)d_in[16];
    const float* W_rd       = (const float*)d_in[17];
    const float* b_rd       = (const float*)d_in[18];
    float* out = (float*)d_out;

    cudaFuncSetAttribute(k57_mem_link, cudaFuncAttributeMaxDynamicSharedMemorySize, SMEM_DYN);

    k1_zpart<<<dim3(4, 16), 256>>>(x, h_prev, rv_prev, Wx, Wh);
    k2_lstm<<<16, 512>>>(c_prev, b_lstm);
    k3_iface<<<46, 256>>>(W_if, W_hid, b_if, b_hid);
    k4b_rank<<<dim3(8, B), 256>>>(rw_prev, ww_prev, usage_prev, mem_prev);
    k4c_alloc<<<B, 512>>>(rw_prev, prec_prev);
    k57_mem_link<<<dim3(8, B), 512, SMEM_DYN>>>(mem_prev, link_prev, rw_prev);
    k8_read_out<<<B, 512>>>(rw_prev, prec_prev, W_rd, b_rd, out);
}

// round 8
// speedup vs baseline: 1.0499x; 1.0499x over previous
#include <cuda_runtime.h>
#include <math.h>

#define B 16
#define I_IN 256
#define H 512
#define O_OUT 256
#define A 1024
#define M 64
#define R 4
#define IFW 471
#define N4H 2048
#define NCOLS3 (IFW + O_OUT)   // 727

// interface offsets
#define OFF_KR     0
#define OFF_BETAR  256
#define OFF_KW     260
#define OFF_BETAW  324
#define OFF_ERASE  325
#define OFF_WRITEV 389
#define OFF_FREE   453
#define OFF_GA     457
#define OFF_GW     458
#define OFF_PI     459

// ----------------- device scratch -----------------
__device__ float  g_zpart[16][B][N4H];
__device__ float  g_h[B][H];
__device__ float  g_iface[B][IFW];
__device__ float  g_outhid[B][O_OUT];
__device__ float  g_usage[B][A];
__device__ int    g_rank[B][A];
__device__ float  g_cwlog[B][A];
__device__ float  g_ww[B][A];
__device__ float  g_S[B][R];
__device__ float  g_T[B][R];
__device__ float  g_mem[B][A][M];
__device__ float  g_cr[B][R][A];
__device__ double g_PQ[B][R][A];        // packed (p,q)
__device__ double g_UVp[16][B][R][A];   // packed (u,v) partials, 2 per stripe

__device__ __forceinline__ float sigf(float x) { return 1.f / (1.f + __expf(-x)); }
__device__ __forceinline__ float oneplusf(float x) {
    return 1.f + (x > 20.f ? x : log1pf(__expf(x)));
}

// packed f32x2 helpers (double as bit-carrier)
__device__ __forceinline__ double pack2(float lo, float hi) {
    double d; asm("mov.b64 %0, {%1,%2};" : "=d"(d) : "f"(lo), "f"(hi)); return d;
}
__device__ __forceinline__ double splat2(float v) {
    double d; asm("mov.b64 %0, {%1,%1};" : "=d"(d) : "f"(v)); return d;
}
__device__ __forceinline__ void fma2(double& acc, double a, double b) {
    asm("fma.rn.f32x2 %0, %1, %2, %3;" : "=d"(acc) : "d"(a), "d"(b), "d"(acc));
}
__device__ __forceinline__ double add2(double a, double b) {
    double d; asm("add.rn.f32x2 %0, %1, %2;" : "=d"(d) : "d"(a), "d"(b)); return d;
}
__device__ __forceinline__ float2 unpack2(double d) {
    float2 f;
    asm("mov.b64 {%0,%1}, %2;" : "=f"(f.x), "=f"(f.y) : "l"(__double_as_longlong(d)));
    return f;
}

// swizzle for pack table (idx = a*4 + r); flips bits [2:4] only, so idx..idx+3 stay contiguous
__device__ __forceinline__ int swz(int idx) { return idx ^ (((idx >> 9) & 7) << 2); }

template <int NT>
__device__ __forceinline__ float blockSum(float v, float* s_red) {
    int lane = threadIdx.x & 31, w = threadIdx.x >> 5;
#pragma unroll
    for (int o = 16; o; o >>= 1) v += __shfl_down_sync(0xffffffffu, v, o);
    if (lane == 0) s_red[w] = v;
    __syncthreads();
    if (w == 0) {
        float x = (lane < NT / 32) ? s_red[lane] : 0.f;
#pragma unroll
        for (int o = 16; o; o >>= 1) x += __shfl_down_sync(0xffffffffu, x, o);
        if (lane == 0) s_red[0] = x;
    }
    __syncthreads();
    float res = s_red[0];
    __syncthreads();
    return res;
}
template <int NT>
__device__ __forceinline__ float blockMax(float v, float* s_red) {
    int lane = threadIdx.x & 31, w = threadIdx.x >> 5;
#pragma unroll
    for (int o = 16; o; o >>= 1) v = fmaxf(v, __shfl_down_sync(0xffffffffu, v, o));
    if (lane == 0) s_red[w] = v;
    __syncthreads();
    if (w == 0) {
        float x = (lane < NT / 32) ? s_red[lane] : -1e30f;
#pragma unroll
        for (int o = 16; o; o >>= 1) x = fmaxf(x, __shfl_down_sync(0xffffffffu, x, o));
        if (lane == 0) s_red[0] = x;
    }
    __syncthreads();
    float res = s_red[0];
    __syncthreads();
    return res;
}

// ============ K1: z GEMM, k-split 16 chunks of 64, packed f32x2 ============
__global__ void __launch_bounds__(256, 1)
k1_zpart(const float* __restrict__ x, const float* __restrict__ h_prev,
         const float* __restrict__ rv_prev, const float* __restrict__ Wx,
         const float* __restrict__ Wh) {
    __shared__ double s_in2[B][64];
    int tid = threadIdx.x;
    int ntile = blockIdx.x;
    int kc = blockIdx.y;
    int kbase = kc * 64;
    for (int idx = tid; idx < B * 64; idx += 256) {
        int b = idx >> 6, kl = idx & 63;
        int kk = kbase + kl;
        float v;
        if (kk < 256) v = x[b * I_IN + kk];
        else if (kk < 512) v = rv_prev[b * 256 + (kk - 256)];
        else v = h_prev[b * H + (kk - 512)];
        s_in2[b][kl] = splat2(v);
    }
    __syncthreads();
    int n0 = ntile * 512 + tid * 2;
    const float* Wbase = (kbase < 512) ? (Wx + (size_t)kbase * N4H)
                                       : (Wh + (size_t)(kbase - 512) * N4H);
    const char* Wp = (const char*)(Wbase + n0);
    double acc2[B];
#pragma unroll
    for (int b = 0; b < B; b++) acc2[b] = 0.0;
#pragma unroll 4
    for (int kl = 0; kl < 64; kl++) {
        double w2 = *(const double*)(Wp + (size_t)kl * (N4H * 4));
#pragma unroll
        for (int b = 0; b < B; b++) fma2(acc2[b], s_in2[b][kl], w2);
    }
#pragma unroll
    for (int b = 0; b < B; b++)
        *(double*)&g_zpart[kc][b][n0] = acc2[b];
}

// ============ K2: reduce z partials + LSTM ============
__global__ void __launch_bounds__(512, 1)
k2_lstm(const float* __restrict__ c_prev, const float* __restrict__ b_lstm) {
    int idx = blockIdx.x * 512 + threadIdx.x;
    int b = idx >> 9, hh = idx & 511;
    float zv[4];
#pragma unroll
    for (int g = 0; g < 4; g++) {
        int n = g * H + hh;
        float s = b_lstm[n];
#pragma unroll
        for (int kc = 0; kc < 16; kc++) s += g_zpart[kc][b][n];
        zv[g] = s;
    }
    float c = sigf(zv[1]) * c_prev[idx] + sigf(zv[0]) * tanhf(zv[2]);
    g_h[b][hh] = sigf(zv[3]) * tanhf(c);
}

// ============ K3: iface + out_hidden GEMM, full K, split accumulators ============
__global__ void __launch_bounds__(256, 1)
k3_iface(const float* __restrict__ W_if, const float* __restrict__ W_hid,
         const float* __restrict__ b_if, const float* __restrict__ b_hid) {
    int idx = blockIdx.x * 256 + threadIdx.x;
    if (idx >= B * NCOLS3) return;
    int col = idx % NCOLS3, b = idx / NCOLS3;
    const float* hrow = g_h[b];
    float a0 = 0.f, a1 = 0.f, a2 = 0.f, a3 = 0.f;
    if (col < IFW) {
        const float* W = W_if + col;
#pragma unroll 4
        for (int k = 0; k < H; k += 4) {
            a0 = fmaf(hrow[k],     W[(size_t)(k)     * IFW], a0);
            a1 = fmaf(hrow[k + 1], W[(size_t)(k + 1) * IFW], a1);
            a2 = fmaf(hrow[k + 2], W[(size_t)(k + 2) * IFW], a2);
            a3 = fmaf(hrow[k + 3], W[(size_t)(k + 3) * IFW], a3);
        }
        g_iface[b][col] = (a0 + a1) + (a2 + a3) + b_if[col];
    } else {
        int c2 = col - IFW;
        const float* W = W_hid + c2;
#pragma unroll 4
        for (int k = 0; k < H; k += 4) {
            a0 = fmaf(hrow[k],     W[(size_t)(k)     * O_OUT], a0);
            a1 = fmaf(hrow[k + 1], W[(size_t)(k + 1) * O_OUT], a1);
            a2 = fmaf(hrow[k + 2], W[(size_t)(k + 2) * O_OUT], a2);
            a3 = fmaf(hrow[k + 3], W[(size_t)(k + 3) * O_OUT], a3);
        }
        g_outhid[b][c2] = (a0 + a1) + (a2 + a3) + b_hid[c2];
    }
}

// ============ K4b: usage + rank (stable counting argsort) + cwlog ============
// grid (16 chunks, B), 256 threads; chunk owns 64 slots/rows
__global__ void __launch_bounds__(256, 1)
k4b_rank(const float* __restrict__ rw_prev, const float* __restrict__ ww_prev,
         const float* __restrict__ usage_prev, const float* __restrict__ mem_prev) {
    __shared__ float s_u[A];
    __shared__ float s_kw[M];
    __shared__ float s_free[R];
    __shared__ float s_bw[1];
    int tid = threadIdx.x;
    int chunk = blockIdx.x, b = blockIdx.y;

    if (tid < R) s_free[tid] = sigf(g_iface[b][OFF_FREE + tid]);
    if (tid < M) s_kw[tid] = g_iface[b][OFF_KW + tid];
    if (tid == 0) s_bw[0] = oneplusf(g_iface[b][OFF_BETAW]);
    __syncthreads();

    // usage for all A (redundant per chunk; latency hidden by occupancy)
#pragma unroll
    for (int ii = 0; ii < 4; ii++) {
        int a = tid + ii * 256;
        float psi = 1.f;
#pragma unroll
        for (int r = 0; r < R; r++)
            psi *= (1.f - s_free[r] * rw_prev[(b * R + r) * A + a]);
        float u = usage_prev[b * A + a], w = ww_prev[b * A + a];
        s_u[a] = (u + w - u * w) * psi;
    }
    __syncthreads();
    if (tid < 64) g_usage[b][chunk * 64 + tid] = s_u[chunk * 64 + tid];

    // rank: 4 threads per slot, each scans 256 values
    {
        int slot = chunk * 64 + (tid >> 2);
        int part = tid & 3;
        float u = s_u[slot];
        int cnt = 0;
        const float4* uu = reinterpret_cast<const float4*>(&s_u[part * 256]);
        int base = part * 256;
#pragma unroll 8
        for (int i = 0; i < 64; i++) {
            float4 v = uu[i];
            int ap = base + i * 4;
            cnt += (v.x < u) || (v.x == u && (ap + 0) < slot);
            cnt += (v.y < u) || (v.y == u && (ap + 1) < slot);
            cnt += (v.z < u) || (v.z == u && (ap + 2) < slot);
            cnt += (v.w < u) || (v.w == u && (ap + 3) < slot);
        }
        cnt += __shfl_xor_sync(0xffffffffu, cnt, 1);
        cnt += __shfl_xor_sync(0xffffffffu, cnt, 2);
        if (part == 0) g_rank[b][slot] = cnt;
    }

    // cwlog: 4 threads per row, each 16 floats
    {
        int row = chunk * 64 + (tid >> 2);
        int part = tid & 3;
        const float4* mrow =
            reinterpret_cast<const float4*>(mem_prev + ((size_t)(b * A + row)) * M) + part * 4;
        float d = 0.f, n = 0.f;
#pragma unroll
        for (int q = 0; q < 4; q++) {
            float4 v = mrow[q];
            int m0 = part * 16 + q * 4;
            d += v.x * s_kw[m0] + v.y * s_kw[m0 + 1] + v.z * s_kw[m0 + 2] + v.w * s_kw[m0 + 3];
            n += v.x * v.x + v.y * v.y + v.z * v.z + v.w * v.w;
        }
        d += __shfl_xor_sync(0xffffffffu, d, 1);
        n += __shfl_xor_sync(0xffffffffu, n, 1);
        d += __shfl_xor_sync(0xffffffffu, d, 2);
        n += __shfl_xor_sync(0xffffffffu, n, 2);
        if (part == 0) {
            float kn2 = 0.f;
#pragma unroll
            for (int m = 0; m < M; m++) { float v = s_kw[m]; kn2 = fmaf(v, v, kn2); }
            g_cwlog[b][row] = s_bw[0] * d / (sqrtf(kn2) * sqrtf(n) + 1e-6f);
        }
    }
}

// ============ K4c: scatter + cumprod + alloc + cw softmax + ww + S,T ============
__global__ void __launch_bounds__(512, 1)
k4c_alloc(const float* __restrict__ rw_prev, const float* __restrict__ prec_prev) {
    int b = blockIdx.x;
    int tid = threadIdx.x;  // 512
    __shared__ float s_sorted[A];
    __shared__ float s_tmp[A];
    __shared__ float s_cw[A];
    __shared__ float s_red[16];
    __shared__ float s_scal[4];

    if (tid == 0) {
        s_scal[0] = sigf(g_iface[b][OFF_GA]);
        s_scal[1] = sigf(g_iface[b][OFF_GW]);
    }

    float u0 = g_usage[b][tid], u1 = g_usage[b][tid + 512];
    int r0 = g_rank[b][tid], r1 = g_rank[b][tid + 512];
    s_sorted[r0] = u0;
    s_sorted[r1] = u1;
    __syncthreads();

    // inclusive cumprod (Hillis-Steele, 10 steps)
    float* src = s_sorted;
    float* dst = s_tmp;
    for (int off = 1; off < A; off <<= 1) {
        for (int i = tid; i < A; i += 512)
            dst[i] = (i >= off) ? src[i - off] * src[i] : src[i];
        __syncthreads();
        float* t = src; src = dst; dst = t;
    }
    // alloc
    float alloc0 = (1.f - u0) * (r0 == 0 ? 1.f : src[r0 - 1]);
    float alloc1 = (1.f - u1) * (r1 == 0 ? 1.f : src[r1 - 1]);

    // c_w softmax
    float l0 = g_cwlog[b][tid], l1 = g_cwlog[b][tid + 512];
    float mx = blockMax<512>(fmaxf(l0, l1), s_red);
    float e0 = __expf(l0 - mx), e1 = __expf(l1 - mx);
    float ssum = blockSum<512>(e0 + e1, s_red);
    float inv = 1.f / ssum;
    s_cw[tid] = e0 * inv;
    s_cw[tid + 512] = e1 * inv;
    __syncthreads();

    float ga = s_scal[0], gw = s_scal[1];
    float sS[R] = {0, 0, 0, 0}, sT[R] = {0, 0, 0, 0};
    float wwv0 = gw * (ga * alloc0 + (1.f - ga) * s_cw[tid]);
    float wwv1 = gw * (ga * alloc1 + (1.f - ga) * s_cw[tid + 512]);
    g_ww[b][tid] = wwv0;
    g_ww[b][tid + 512] = wwv1;
    {
        float pp0 = prec_prev[b * A + tid], pp1 = prec_prev[b * A + tid + 512];
#pragma unroll
        for (int r = 0; r < R; r++) {
            float rw0 = rw_prev[(b * R + r) * A + tid];
            float rw1 = rw_prev[(b * R + r) * A + tid + 512];
            sS[r] = fmaf(pp0, rw0, fmaf(pp1, rw1, sS[r]));
            sT[r] = fmaf(wwv0, rw0, fmaf(wwv1, rw1, sT[r]));
        }
    }
#pragma unroll
    for (int r = 0; r < R; r++) {
        float v = blockSum<512>(sS[r], s_red);
        if (tid == 0) g_S[b][r] = v;
        v = blockSum<512>(sT[r], s_red);
        if (tid == 0) g_T[b][r] = v;
    }
}

// ============ K57: mem write + c_r logits + link pass (R3 direct-load version) ====
__global__ void __launch_bounds__(512, 1)
k57_mem_link(const float* __restrict__ mem_prev, const float* __restrict__ link_prev,
             const float* __restrict__ rw_prev) {
    __shared__ double s_pack[A * 4];          // 32 KB
    __shared__ float  s_kr[R][M];
    __shared__ float  s_er[M], s_wv[M];
    __shared__ float  s_beta[R], s_kn[R];
    int tid = threadIdx.x;                    // 512
    int stripe = blockIdx.x;                  // 8 stripes of 128 rows
    int b = blockIdx.y;
    int jbase = stripe * 128;

    // --- params ---
    if (tid < 256) {
        int r = tid >> 6, m = tid & 63;
        s_kr[r][m] = g_iface[b][OFF_KR + r * M + m];
    } else if (tid < 256 + M) {
        s_er[tid - 256] = sigf(g_iface[b][OFF_ERASE + (tid - 256)]);
    } else if (tid < 256 + 2 * M) {
        s_wv[tid - 256 - M] = g_iface[b][OFF_WRITEV + (tid - 256 - M)];
    }
    __syncthreads();
    if (tid < R) {
        s_beta[tid] = oneplusf(g_iface[b][OFF_BETAR + tid]);
        float s = 0.f;
#pragma unroll
        for (int m = 0; m < M; m++) { float v = s_kr[tid][m]; s = fmaf(v, v, s); }
        s_kn[tid] = sqrtf(s);
    }
    __syncthreads();

    // --- part 1: mem update + cr logits for rows [jbase, jbase+128) ---
    {
        int lane16 = tid & 15, m0 = lane16 * 4;
#pragma unroll
        for (int pass = 0; pass < 4; pass++) {
            int a = jbase + pass * 32 + (tid >> 4);
            float w = g_ww[b][a];
            float4 v = *reinterpret_cast<const float4*>(mem_prev + ((size_t)(b * A + a)) * M + m0);
            float n0 = v.x * (1.f - w * s_er[m0])     + w * s_wv[m0];
            float n1 = v.y * (1.f - w * s_er[m0 + 1]) + w * s_wv[m0 + 1];
            float n2 = v.z * (1.f - w * s_er[m0 + 2]) + w * s_wv[m0 + 2];
            float n3 = v.w * (1.f - w * s_er[m0 + 3]) + w * s_wv[m0 + 3];
            *reinterpret_cast<float4*>(&g_mem[b][a][m0]) = make_float4(n0, n1, n2, n3);
            float nn = n0 * n0 + n1 * n1 + n2 * n2 + n3 * n3;
            float d[R];
#pragma unroll
            for (int r = 0; r < R; r++)
                d[r] = n0 * s_kr[r][m0] + n1 * s_kr[r][m0 + 1] +
                       n2 * s_kr[r][m0 + 2] + n3 * s_kr[r][m0 + 3];
#pragma unroll
            for (int o = 8; o; o >>= 1) {
                nn += __shfl_xor_sync(0xffffffffu, nn, o);
#pragma unroll
                for (int r = 0; r < R; r++) d[r] += __shfl_xor_sync(0xffffffffu, d[r], o);
            }
            if (lane16 == 0) {
                float mn = sqrtf(nn);
#pragma unroll
                for (int r = 0; r < R; r++)
                    g_cr[b][r][a] = s_beta[r] * d[r] / (s_kn[r] * mn + 1e-6f);
            }
        }
    }

    // --- pack table ---
    for (int a = tid; a < A; a += 512) {
        float w = g_ww[b][a];
#pragma unroll
        for (int r = 0; r < R; r++) {
            float rw = rw_prev[(b * R + r) * A + a];
            s_pack[swz(a * 4 + r)] = pack2(rw, w * rw);
        }
    }
    __syncthreads();

    const float* Lp = link_prev + (size_t)b * A * A;

    // --- phase A: column partials (u,v); thread owns 4 cols, half the rows ---
    {
        int colbase = 4 * (tid & 255);
        int rhalf = tid >> 8;  // 0 or 1
        double uv[4][R];
#pragma unroll
        for (int c = 0; c < 4; c++)
#pragma unroll
            for (int r = 0; r < R; r++) uv[c][r] = 0.0;
#pragma unroll 4
        for (int i = 0; i < 64; i++) {
            int j = jbase + 2 * i + rhalf;
            float4 val = *reinterpret_cast<const float4*>(Lp + (size_t)j * A + colbase);
            int j4 = j * 4;
            double2 pk01 = *reinterpret_cast<const double2*>(&s_pack[swz(j4)]);
            double2 pk23 = *reinterpret_cast<const double2*>(&s_pack[swz(j4 + 2)]);
            double sx = splat2(val.x), sy = splat2(val.y);
            double sz = splat2(val.z), sw = splat2(val.w);
            fma2(uv[0][0], sx, pk01.x); fma2(uv[0][1], sx, pk01.y);
            fma2(uv[0][2], sx, pk23.x); fma2(uv[0][3], sx, pk23.y);
            fma2(uv[1][0], sy, pk01.x); fma2(uv[1][1], sy, pk01.y);
            fma2(uv[1][2], sy, pk23.x); fma2(uv[1][3], sy, pk23.y);
            fma2(uv[2][0], sz, pk01.x); fma2(uv[2][1], sz, pk01.y);
            fma2(uv[2][2], sz, pk23.x); fma2(uv[2][3], sz, pk23.y);
            fma2(uv[3][0], sw, pk01.x); fma2(uv[3][1], sw, pk01.y);
            fma2(uv[3][2], sw, pk23.x); fma2(uv[3][3], sw, pk23.y);
        }
        int sidx = 2 * stripe + rhalf;
#pragma unroll
        for (int c = 0; c < 4; c++)
#pragma unroll
            for (int r = 0; r < R; r++)
                g_UVp[sidx][b][r][colbase + c] = uv[c][r];
    }

    // --- phase B: row dots (p,q); 4 threads per row, 256 cols each (L2-hot) ---
    {
        int rowl = tid >> 2, quarter = tid & 3;
        int row = jbase + rowl;
        int cbase = quarter * 256;
        const float* Lr = Lp + (size_t)row * A + cbase;
        double pq[R] = {0.0, 0.0, 0.0, 0.0};
#pragma unroll 4
        for (int cs = 0; cs < 64; cs++) {
            float4 val = *reinterpret_cast<const float4*>(Lr + cs * 4);
            int col4 = (cbase + cs * 4) * 4;
            {
                double2 pk01 = *reinterpret_cast<const double2*>(&s_pack[swz(col4)]);
                double2 pk23 = *reinterpret_cast<const double2*>(&s_pack[swz(col4 + 2)]);
                double s = splat2(val.x);
                fma2(pq[0], s, pk01.x); fma2(pq[1], s, pk01.y);
                fma2(pq[2], s, pk23.x); fma2(pq[3], s, pk23.y);
            }
            {
                double2 pk01 = *reinterpret_cast<const double2*>(&s_pack[swz(col4 + 4)]);
                double2 pk23 = *reinterpret_cast<const double2*>(&s_pack[swz(col4 + 6)]);
                double s = splat2(val.y);
                fma2(pq[0], s, pk01.x); fma2(pq[1], s, pk01.y);
                fma2(pq[2], s, pk23.x); fma2(pq[3], s, pk23.y);
            }
            {
                double2 pk01 = *reinterpret_cast<const double2*>(&s_pack[swz(col4 + 8)]);
                double2 pk23 = *reinterpret_cast<const double2*>(&s_pack[swz(col4 + 10)]);
                double s = splat2(val.z);
                fma2(pq[0], s, pk01.x); fma2(pq[1], s, pk01.y);
                fma2(pq[2], s, pk23.x); fma2(pq[3], s, pk23.y);
            }
            {
                double2 pk01 = *reinterpret_cast<const double2*>(&s_pack[swz(col4 + 12)]);
                double2 pk23 = *reinterpret_cast<const double2*>(&s_pack[swz(col4 + 14)]);
                double s = splat2(val.w);
                fma2(pq[0], s, pk01.x); fma2(pq[1], s, pk01.y);
                fma2(pq[2], s, pk23.x); fma2(pq[3], s, pk23.y);
            }
        }
#pragma unroll
        for (int r = 0; r < R; r++) {
            pq[r] = add2(pq[r], __shfl_xor_sync(0xffffffffu, pq[r], 1));
            pq[r] = add2(pq[r], __shfl_xor_sync(0xffffffffu, pq[r], 2));
        }
        if (quarter == 0) {
#pragma unroll
            for (int r = 0; r < R; r++) g_PQ[b][r][row] = pq[r];
        }
    }
}

// ============ K8: cr softmax + read weights + rv GEMV + output (1 block/b) ====
__global__ void __launch_bounds__(512, 1)
k8_read_out(const float* __restrict__ rw_prev, const float* __restrict__ prec_prev,
            const float* __restrict__ W_rd, const float* __restrict__ b_rd,
            float* __restrict__ out) {
    int b = blockIdx.x;
    int tid = threadIdx.x;  // 512
    __shared__ float s_wr[R][A];
    __shared__ float s_racc[16][R][M];
    __shared__ float s_rv[R * M];
    __shared__ float s_out[2][O_OUT];
    __shared__ float s_pi[R][3];
    __shared__ float s_red[16];

    if (tid < R) {
        float l0 = g_iface[b][OFF_PI + tid * 3 + 0];
        float l1 = g_iface[b][OFF_PI + tid * 3 + 1];
        float l2 = g_iface[b][OFF_PI + tid * 3 + 2];
        float mx = fmaxf(l0, fmaxf(l1, l2));
        float e0 = __expf(l0 - mx), e1 = __expf(l1 - mx), e2 = __expf(l2 - mx);
        float inv = 1.f / (e0 + e1 + e2);
        s_pi[tid][0] = e0 * inv; s_pi[tid][1] = e1 * inv; s_pi[tid][2] = e2 * inv;
    }

#pragma unroll
    for (int r = 0; r < R; r++) {
        float l0 = g_cr[b][r][tid], l1 = g_cr[b][r][tid + 512];
        float mx = blockMax<512>(fmaxf(l0, l1), s_red);
        float e0 = __expf(l0 - mx), e1 = __expf(l1 - mx);
        float s = blockSum<512>(e0 + e1, s_red);
        float inv = 1.f / s;
        s_wr[r][tid] = e0 * inv;
        s_wr[r][tid + 512] = e1 * inv;
    }
    __syncthreads();

    for (int ii = 0; ii < 2; ii++) {
        int a = tid + ii * 512;
        float ww = g_ww[b][a];
        float pp = prec_prev[b * A + a];
#pragma unroll
        for (int r = 0; r < R; r++) {
            float rw = rw_prev[(b * R + r) * A + a];
            float2 PQ = unpack2(g_PQ[b][r][a]);
            double uvs = g_UVp[0][b][r][a];
#pragma unroll
            for (int s16 = 1; s16 < 16; s16++) uvs = add2(uvs, g_UVp[s16][b][r][a]);
            float2 UV = unpack2(uvs);
            float Sr = g_S[b][r], Tr = g_T[b][r];
            float fwd = (1.f - ww) * PQ.x - PQ.y + ww * (Sr - pp * rw);
            float bwd = (1.f - ww) * UV.x - UV.y + pp * (Tr - ww * rw);
            float cr = s_wr[r][a];
            s_wr[r][a] = s_pi[r][0] * bwd + s_pi[r][1] * cr + s_pi[r][2] * fwd;
        }
    }
    __syncthreads();

    {
        int w = tid >> 5, lane = tid & 31;
        float acc[2][R] = {{0, 0, 0, 0}, {0, 0, 0, 0}};
#pragma unroll 4
        for (int i = 0; i < 64; i++) {
            int a = i * 16 + w;
            float m0 = g_mem[b][a][lane];
            float m1 = g_mem[b][a][lane + 32];
#pragma unroll
            for (int r = 0; r < R; r++) {
                float wr = s_wr[r][a];
                acc[0][r] = fmaf(wr, m0, acc[0][r]);
                acc[1][r] = fmaf(wr, m1, acc[1][r]);
            }
        }
#pragma unroll
        for (int r = 0; r < R; r++) {
            s_racc[w][r][lane] = acc[0][r];
            s_racc[w][r][lane + 32] = acc[1][r];
        }
    }
    __syncthreads();
    if (tid < R * M) {
        float s = 0.f;
#pragma unroll
        for (int w = 0; w < 16; w++) s += s_racc[w][tid >> 6][tid & 63];
        s_rv[tid] = s;
    }
    __syncthreads();

    {
        int half = tid >> 8, col = tid & 255;
        float acc = 0.f;
        const float* W = W_rd + (size_t)half * 128 * O_OUT + col;
#pragma unroll 8
        for (int j = 0; j < 128; j++)
            acc = fmaf(s_rv[half * 128 + j], W[(size_t)j * O_OUT], acc);
        s_out[half][col] = acc;
    }
    __syncthreads();
    if (tid < O_OUT) {
        out[b * O_OUT + tid] = s_out[0][tid] + s_out[1][tid] + g_outhid[b][tid] + b_rd[tid];
    }
}

// ----------------- launch -----------------
extern "C" void kernel_launch(void* const* d_in, const int* in_sizes, int n_in,
                              void* d_out, int out_size) {
    (void)in_sizes; (void)n_in; (void)out_size;
    const float* x          = (const float*)d_in[0];
    const float* h_prev     = (const float*)d_in[1];
    const float* c_prev     = (const float*)d_in[2];
    const float* mem_prev   = (const float*)d_in[3];
    const float* rw_prev    = (const float*)d_in[4];
    const float* ww_prev    = (const float*)d_in[5];
    const float* usage_prev = (const float*)d_in[6];
    const float* prec_prev  = (const float*)d_in[7];
    const float* link_prev  = (const float*)d_in[8];
    const float* rv_prev    = (const float*)d_in[9];
    const float* Wx         = (const float*)d_in[10];
    const float* Wh         = (const float*)d_in[11];
    const float* b_lstm     = (const float*)d_in[12];
    const float* W_hid      = (const float*)d_in[13];
    const float* b_hid      = (const float*)d_in[14];
    const float* W_if       = (const float*)d_in[15];
    const float* b_if       = (const float*)d_in[16];
    const float* W_rd       = (const float*)d_in[17];
    const float* b_rd       = (const float*)d_in[18];
    float* out = (float*)d_out;

    k1_zpart<<<dim3(4, 16), 256>>>(x, h_prev, rv_prev, Wx, Wh);
    k2_lstm<<<16, 512>>>(c_prev, b_lstm);
    k3_iface<<<46, 256>>>(W_if, W_hid, b_if, b_hid);
    k4b_rank<<<dim3(16, B), 256>>>(rw_prev, ww_prev, usage_prev, mem_prev);
    k4c_alloc<<<B, 512>>>(rw_prev, prec_prev);
    k57_mem_link<<<dim3(8, B), 512>>>(mem_prev, link_prev, rw_prev);
    k8_read_out<<<B, 512>>>(rw_prev, prec_prev, W_rd, b_rd, out);
}

// round 9
// speedup vs baseline: 1.0667x; 1.0160x over previous
#include <cuda_runtime.h>
#include <math.h>

#define B 16
#define I_IN 256
#define H 512
#define O_OUT 256
#define A 1024
#define M 64
#define R 4
#define IFW 471
#define N4H 2048
#define NCOLS3 (IFW + O_OUT)   // 727

// interface offsets
#define OFF_KR     0
#define OFF_BETAR  256
#define OFF_KW     260
#define OFF_BETAW  324
#define OFF_ERASE  325
#define OFF_WRITEV 389
#define OFF_FREE   453
#define OFF_GA     457
#define OFF_GW     458
#define OFF_PI     459

// ----------------- device scratch -----------------
__device__ float  g_zpart[16][B][N4H];
__device__ float  g_h[B][H];
__device__ float  g_iface[B][IFW];
__device__ float  g_outhid[B][O_OUT];
__device__ float  g_usage[B][A];
__device__ int    g_rank[B][A];
__device__ float  g_cwlog[B][A];
__device__ float  g_ww[B][A];
__device__ float  g_S[B][R];
__device__ float  g_T[B][R];
__device__ float  g_mem[B][A][M];
__device__ float  g_cr[B][R][A];
__device__ double g_PQ[B][R][A];        // packed (p,q)
__device__ double g_UVp[16][B][R][A];   // packed (u,v) partials, 2 per stripe
__device__ double g_UV[B][R][A];        // reduced (u,v)

__device__ __forceinline__ float sigf(float x) { return 1.f / (1.f + __expf(-x)); }
__device__ __forceinline__ float oneplusf(float x) {
    return 1.f + (x > 20.f ? x : log1pf(__expf(x)));
}

// packed f32x2 helpers (double as bit-carrier)
__device__ __forceinline__ double pack2(float lo, float hi) {
    double d; asm("mov.b64 %0, {%1,%2};" : "=d"(d) : "f"(lo), "f"(hi)); return d;
}
__device__ __forceinline__ double splat2(float v) {
    double d; asm("mov.b64 %0, {%1,%1};" : "=d"(d) : "f"(v)); return d;
}
__device__ __forceinline__ void fma2(double& acc, double a, double b) {
    asm("fma.rn.f32x2 %0, %1, %2, %3;" : "=d"(acc) : "d"(a), "d"(b), "d"(acc));
}
__device__ __forceinline__ double add2(double a, double b) {
    double d; asm("add.rn.f32x2 %0, %1, %2;" : "=d"(d) : "d"(a), "d"(b)); return d;
}
__device__ __forceinline__ float2 unpack2(double d) {
    float2 f;
    asm("mov.b64 {%0,%1}, %2;" : "=f"(f.x), "=f"(f.y) : "l"(__double_as_longlong(d)));
    return f;
}

// swizzle for pack table (idx = a*4 + r); flips bits [2:4] only, so idx..idx+3 stay contiguous
__device__ __forceinline__ int swz(int idx) { return idx ^ (((idx >> 9) & 7) << 2); }

template <int NT>
__device__ __forceinline__ float blockSum(float v, float* s_red) {
    int lane = threadIdx.x & 31, w = threadIdx.x >> 5;
#pragma unroll
    for (int o = 16; o; o >>= 1) v += __shfl_down_sync(0xffffffffu, v, o);
    if (lane == 0) s_red[w] = v;
    __syncthreads();
    if (w == 0) {
        float x = (lane < NT / 32) ? s_red[lane] : 0.f;
#pragma unroll
        for (int o = 16; o; o >>= 1) x += __shfl_down_sync(0xffffffffu, x, o);
        if (lane == 0) s_red[0] = x;
    }
    __syncthreads();
    float res = s_red[0];
    __syncthreads();
    return res;
}
template <int NT>
__device__ __forceinline__ float blockMax(float v, float* s_red) {
    int lane = threadIdx.x & 31, w = threadIdx.x >> 5;
#pragma unroll
    for (int o = 16; o; o >>= 1) v = fmaxf(v, __shfl_down_sync(0xffffffffu, v, o));
    if (lane == 0) s_red[w] = v;
    __syncthreads();
    if (w == 0) {
        float x = (lane < NT / 32) ? s_red[lane] : -1e30f;
#pragma unroll
        for (int o = 16; o; o >>= 1) x = fmaxf(x, __shfl_down_sync(0xffffffffu, x, o));
        if (lane == 0) s_red[0] = x;
    }
    __syncthreads();
    float res = s_red[0];
    __syncthreads();
    return res;
}

// ============ K1: z GEMM, k-split 16 chunks of 64, packed f32x2 ============
__global__ void __launch_bounds__(256, 1)
k1_zpart(const float* __restrict__ x, const float* __restrict__ h_prev,
         const float* __restrict__ rv_prev, const float* __restrict__ Wx,
         const float* __restrict__ Wh) {
    __shared__ double s_in2[B][64];
    int tid = threadIdx.x;
    int ntile = blockIdx.x;
    int kc = blockIdx.y;
    int kbase = kc * 64;
    for (int idx = tid; idx < B * 64; idx += 256) {
        int b = idx >> 6, kl = idx & 63;
        int kk = kbase + kl;
        float v;
        if (kk < 256) v = x[b * I_IN + kk];
        else if (kk < 512) v = rv_prev[b * 256 + (kk - 256)];
        else v = h_prev[b * H + (kk - 512)];
        s_in2[b][kl] = splat2(v);
    }
    __syncthreads();
    int n0 = ntile * 512 + tid * 2;
    const float* Wbase = (kbase < 512) ? (Wx + (size_t)kbase * N4H)
                                       : (Wh + (size_t)(kbase - 512) * N4H);
    const char* Wp = (const char*)(Wbase + n0);
    double acc2[B];
#pragma unroll
    for (int b = 0; b < B; b++) acc2[b] = 0.0;
#pragma unroll 4
    for (int kl = 0; kl < 64; kl++) {
        double w2 = *(const double*)(Wp + (size_t)kl * (N4H * 4));
#pragma unroll
        for (int b = 0; b < B; b++) fma2(acc2[b], s_in2[b][kl], w2);
    }
#pragma unroll
    for (int b = 0; b < B; b++)
        *(double*)&g_zpart[kc][b][n0] = acc2[b];
}

// ============ K2: reduce z partials + LSTM ============
__global__ void __launch_bounds__(128, 1)
k2_lstm(const float* __restrict__ c_prev, const float* __restrict__ b_lstm) {
    int idx = blockIdx.x * 128 + threadIdx.x;   // 64 blocks over B*H = 8192
    int b = idx >> 9, hh = idx & 511;
    float zv[4];
#pragma unroll
    for (int g = 0; g < 4; g++) {
        int n = g * H + hh;
        float s = b_lstm[n];
#pragma unroll
        for (int kc = 0; kc < 16; kc++) s += g_zpart[kc][b][n];
        zv[g] = s;
    }
    float c = sigf(zv[1]) * c_prev[idx] + sigf(zv[0]) * tanhf(zv[2]);
    g_h[b][hh] = sigf(zv[3]) * tanhf(c);
}

// ============ K3: iface + out_hidden GEMM, full K, split accumulators ============
__global__ void __launch_bounds__(256, 1)
k3_iface(const float* __restrict__ W_if, const float* __restrict__ W_hid,
         const float* __restrict__ b_if, const float* __restrict__ b_hid) {
    int idx = blockIdx.x * 256 + threadIdx.x;
    if (idx >= B * NCOLS3) return;
    int col = idx % NCOLS3, b = idx / NCOLS3;
    const float* hrow = g_h[b];
    float a0 = 0.f, a1 = 0.f, a2 = 0.f, a3 = 0.f;
    if (col < IFW) {
        const float* W = W_if + col;
#pragma unroll 4
        for (int k = 0; k < H; k += 4) {
            a0 = fmaf(hrow[k],     W[(size_t)(k)     * IFW], a0);
            a1 = fmaf(hrow[k + 1], W[(size_t)(k + 1) * IFW], a1);
            a2 = fmaf(hrow[k + 2], W[(size_t)(k + 2) * IFW], a2);
            a3 = fmaf(hrow[k + 3], W[(size_t)(k + 3) * IFW], a3);
        }
        g_iface[b][col] = (a0 + a1) + (a2 + a3) + b_if[col];
    } else {
        int c2 = col - IFW;
        const float* W = W_hid + c2;
#pragma unroll 4
        for (int k = 0; k < H; k += 4) {
            a0 = fmaf(hrow[k],     W[(size_t)(k)     * O_OUT], a0);
            a1 = fmaf(hrow[k + 1], W[(size_t)(k + 1) * O_OUT], a1);
            a2 = fmaf(hrow[k + 2], W[(size_t)(k + 2) * O_OUT], a2);
            a3 = fmaf(hrow[k + 3], W[(size_t)(k + 3) * O_OUT], a3);
        }
        g_outhid[b][c2] = (a0 + a1) + (a2 + a3) + b_hid[c2];
    }
}

// ============ K0: usage (computed once, wide grid) ============
__global__ void __launch_bounds__(512, 1)
k0_usage(const float* __restrict__ rw_prev, const float* __restrict__ ww_prev,
         const float* __restrict__ usage_prev) {
    int idx = blockIdx.x * 512 + threadIdx.x;   // 32 blocks over B*A
    int b = idx >> 10, a = idx & 1023;
    float psi = 1.f;
#pragma unroll
    for (int r = 0; r < R; r++) {
        float fr = sigf(g_iface[b][OFF_FREE + r]);
        psi *= (1.f - fr * rw_prev[(b * R + r) * A + a]);
    }
    float u = usage_prev[idx], w = ww_prev[idx];
    g_usage[b][a] = (u + w - u * w) * psi;
}

// ============ K4b: rank (broadcast-scan counting argsort) + cwlog ============
// grid (8 chunks, B), 256 threads; chunk owns 128 slots/rows
__global__ void __launch_bounds__(256, 1)
k4b_rank(const float* __restrict__ mem_prev) {
    __shared__ float s_u[A];
    __shared__ float s_kw[M];
    __shared__ float s_bw[1];
    int tid = threadIdx.x;
    int chunk = blockIdx.x, b = blockIdx.y;

    if (tid < M) s_kw[tid] = g_iface[b][OFF_KW + tid];
    if (tid == 0) s_bw[0] = oneplusf(g_iface[b][OFF_BETAW]);
    // load usage (coalesced, once)
    for (int i = tid; i < A; i += 256) s_u[i] = g_usage[b][i];
    __syncthreads();

    // rank: 2 threads per slot; lanes in a warp share the scan index ->
    // LDS broadcast (2 distinct addresses per warp access)
    {
        int slot = chunk * 128 + (tid >> 1);
        int half = tid & 1;
        float u = s_u[slot];
        int cnt = 0;
        int base = half * 512;
#pragma unroll 8
        for (int i = 0; i < 512; i++) {
            float v = s_u[base + i];
            int ia = base + i;
            cnt += (v < u) || (v == u && ia < slot);
        }
        cnt += __shfl_xor_sync(0xffffffffu, cnt, 1);
        if (half == 0) g_rank[b][slot] = cnt;
    }

    // cwlog: 2 threads per row, each 32 floats (8 float4)
    {
        int row = chunk * 128 + (tid >> 1);
        int half = tid & 1;
        const float4* mrow =
            reinterpret_cast<const float4*>(mem_prev + ((size_t)(b * A + row)) * M) + half * 8;
        float d = 0.f, n = 0.f;
#pragma unroll
        for (int q = 0; q < 8; q++) {
            float4 v = mrow[q];
            int m0 = half * 32 + q * 4;
            d += v.x * s_kw[m0] + v.y * s_kw[m0 + 1] + v.z * s_kw[m0 + 2] + v.w * s_kw[m0 + 3];
            n += v.x * v.x + v.y * v.y + v.z * v.z + v.w * v.w;
        }
        d += __shfl_xor_sync(0xffffffffu, d, 1);
        n += __shfl_xor_sync(0xffffffffu, n, 1);
        if (half == 0) {
            float kn2 = 0.f;
#pragma unroll
            for (int m = 0; m < M; m++) { float v = s_kw[m]; kn2 = fmaf(v, v, kn2); }
            g_cwlog[b][row] = s_bw[0] * d / (sqrtf(kn2) * sqrtf(n) + 1e-6f);
        }
    }
}

// ============ K4c: scatter + cumprod + alloc + cw softmax + ww + S,T ============
__global__ void __launch_bounds__(512, 1)
k4c_alloc(const float* __restrict__ rw_prev, const float* __restrict__ prec_prev) {
    int b = blockIdx.x;
    int tid = threadIdx.x;  // 512
    __shared__ float s_sorted[A];
    __shared__ float s_tmp[A];
    __shared__ float s_cw[A];
    __shared__ float s_red[16];
    __shared__ float s_scal[4];

    if (tid == 0) {
        s_scal[0] = sigf(g_iface[b][OFF_GA]);
        s_scal[1] = sigf(g_iface[b][OFF_GW]);
    }

    float u0 = g_usage[b][tid], u1 = g_usage[b][tid + 512];
    int r0 = g_rank[b][tid], r1 = g_rank[b][tid + 512];
    s_sorted[r0] = u0;
    s_sorted[r1] = u1;
    __syncthreads();

    // inclusive cumprod (Hillis-Steele, 10 steps)
    float* src = s_sorted;
    float* dst = s_tmp;
    for (int off = 1; off < A; off <<= 1) {
        for (int i = tid; i < A; i += 512)
            dst[i] = (i >= off) ? src[i - off] * src[i] : src[i];
        __syncthreads();
        float* t = src; src = dst; dst = t;
    }
    // alloc
    float alloc0 = (1.f - u0) * (r0 == 0 ? 1.f : src[r0 - 1]);
    float alloc1 = (1.f - u1) * (r1 == 0 ? 1.f : src[r1 - 1]);

    // c_w softmax
    float l0 = g_cwlog[b][tid], l1 = g_cwlog[b][tid + 512];
    float mx = blockMax<512>(fmaxf(l0, l1), s_red);
    float e0 = __expf(l0 - mx), e1 = __expf(l1 - mx);
    float ssum = blockSum<512>(e0 + e1, s_red);
    float inv = 1.f / ssum;
    s_cw[tid] = e0 * inv;
    s_cw[tid + 512] = e1 * inv;
    __syncthreads();

    float ga = s_scal[0], gw = s_scal[1];
    float sS[R] = {0, 0, 0, 0}, sT[R] = {0, 0, 0, 0};
    float wwv0 = gw * (ga * alloc0 + (1.f - ga) * s_cw[tid]);
    float wwv1 = gw * (ga * alloc1 + (1.f - ga) * s_cw[tid + 512]);
    g_ww[b][tid] = wwv0;
    g_ww[b][tid + 512] = wwv1;
    {
        float pp0 = prec_prev[b * A + tid], pp1 = prec_prev[b * A + tid + 512];
#pragma unroll
        for (int r = 0; r < R; r++) {
            float rw0 = rw_prev[(b * R + r) * A + tid];
            float rw1 = rw_prev[(b * R + r) * A + tid + 512];
            sS[r] = fmaf(pp0, rw0, fmaf(pp1, rw1, sS[r]));
            sT[r] = fmaf(wwv0, rw0, fmaf(wwv1, rw1, sT[r]));
        }
    }
#pragma unroll
    for (int r = 0; r < R; r++) {
        float v = blockSum<512>(sS[r], s_red);
        if (tid == 0) g_S[b][r] = v;
        v = blockSum<512>(sT[r], s_red);
        if (tid == 0) g_T[b][r] = v;
    }
}

// ============ K57: mem write + c_r logits + link pass (R3 direct-load version) ====
__global__ void __launch_bounds__(512, 1)
k57_mem_link(const float* __restrict__ mem_prev, const float* __restrict__ link_prev,
             const float* __restrict__ rw_prev) {
    __shared__ double s_pack[A * 4];          // 32 KB
    __shared__ float  s_kr[R][M];
    __shared__ float  s_er[M], s_wv[M];
    __shared__ float  s_beta[R], s_kn[R];
    int tid = threadIdx.x;                    // 512
    int stripe = blockIdx.x;                  // 8 stripes of 128 rows
    int b = blockIdx.y;
    int jbase = stripe * 128;

    // --- params ---
    if (tid < 256) {
        int r = tid >> 6, m = tid & 63;
        s_kr[r][m] = g_iface[b][OFF_KR + r * M + m];
    } else if (tid < 256 + M) {
        s_er[tid - 256] = sigf(g_iface[b][OFF_ERASE + (tid - 256)]);
    } else if (tid < 256 + 2 * M) {
        s_wv[tid - 256 - M] = g_iface[b][OFF_WRITEV + (tid - 256 - M)];
    }
    __syncthreads();
    if (tid < R) {
        s_beta[tid] = oneplusf(g_iface[b][OFF_BETAR + tid]);
        float s = 0.f;
#pragma unroll
        for (int m = 0; m < M; m++) { float v = s_kr[tid][m]; s = fmaf(v, v, s); }
        s_kn[tid] = sqrtf(s);
    }
    __syncthreads();

    // --- part 1: mem update + cr logits for rows [jbase, jbase+128) ---
    {
        int lane16 = tid & 15, m0 = lane16 * 4;
#pragma unroll
        for (int pass = 0; pass < 4; pass++) {
            int a = jbase + pass * 32 + (tid >> 4);
            float w = g_ww[b][a];
            float4 v = *reinterpret_cast<const float4*>(mem_prev + ((size_t)(b * A + a)) * M + m0);
            float n0 = v.x * (1.f - w * s_er[m0])     + w * s_wv[m0];
            float n1 = v.y * (1.f - w * s_er[m0 + 1]) + w * s_wv[m0 + 1];
            float n2 = v.z * (1.f - w * s_er[m0 + 2]) + w * s_wv[m0 + 2];
            float n3 = v.w * (1.f - w * s_er[m0 + 3]) + w * s_wv[m0 + 3];
            *reinterpret_cast<float4*>(&g_mem[b][a][m0]) = make_float4(n0, n1, n2, n3);
            float nn = n0 * n0 + n1 * n1 + n2 * n2 + n3 * n3;
            float d[R];
#pragma unroll
            for (int r = 0; r < R; r++)
                d[r] = n0 * s_kr[r][m0] + n1 * s_kr[r][m0 + 1] +
                       n2 * s_kr[r][m0 + 2] + n3 * s_kr[r][m0 + 3];
#pragma unroll
            for (int o = 8; o; o >>= 1) {
                nn += __shfl_xor_sync(0xffffffffu, nn, o);
#pragma unroll
                for (int r = 0; r < R; r++) d[r] += __shfl_xor_sync(0xffffffffu, d[r], o);
            }
            if (lane16 == 0) {
                float mn = sqrtf(nn);
#pragma unroll
                for (int r = 0; r < R; r++)
                    g_cr[b][r][a] = s_beta[r] * d[r] / (s_kn[r] * mn + 1e-6f);
            }
        }
    }

    // --- pack table ---
    for (int a = tid; a < A; a += 512) {
        float w = g_ww[b][a];
#pragma unroll
        for (int r = 0; r < R; r++) {
            float rw = rw_prev[(b * R + r) * A + a];
            s_pack[swz(a * 4 + r)] = pack2(rw, w * rw);
        }
    }
    __syncthreads();

    const float* Lp = link_prev + (size_t)b * A * A;

    // --- phase A: column partials (u,v); thread owns 4 cols, half the rows ---
    {
        int colbase = 4 * (tid & 255);
        int rhalf = tid >> 8;  // 0 or 1
        double uv[4][R];
#pragma unroll
        for (int c = 0; c < 4; c++)
#pragma unroll
            for (int r = 0; r < R; r++) uv[c][r] = 0.0;
#pragma unroll 4
        for (int i = 0; i < 64; i++) {
            int j = jbase + 2 * i + rhalf;
            float4 val = *reinterpret_cast<const float4*>(Lp + (size_t)j * A + colbase);
            int j4 = j * 4;
            double2 pk01 = *reinterpret_cast<const double2*>(&s_pack[swz(j4)]);
            double2 pk23 = *reinterpret_cast<const double2*>(&s_pack[swz(j4 + 2)]);
            double sx = splat2(val.x), sy = splat2(val.y);
            double sz = splat2(val.z), sw = splat2(val.w);
            fma2(uv[0][0], sx, pk01.x); fma2(uv[0][1], sx, pk01.y);
            fma2(uv[0][2], sx, pk23.x); fma2(uv[0][3], sx, pk23.y);
            fma2(uv[1][0], sy, pk01.x); fma2(uv[1][1], sy, pk01.y);
            fma2(uv[1][2], sy, pk23.x); fma2(uv[1][3], sy, pk23.y);
            fma2(uv[2][0], sz, pk01.x); fma2(uv[2][1], sz, pk01.y);
            fma2(uv[2][2], sz, pk23.x); fma2(uv[2][3], sz, pk23.y);
            fma2(uv[3][0], sw, pk01.x); fma2(uv[3][1], sw, pk01.y);
            fma2(uv[3][2], sw, pk23.x); fma2(uv[3][3], sw, pk23.y);
        }
        int sidx = 2 * stripe + rhalf;
#pragma unroll
        for (int c = 0; c < 4; c++)
#pragma unroll
            for (int r = 0; r < R; r++)
                g_UVp[sidx][b][r][colbase + c] = uv[c][r];
    }

    // --- phase B: row dots (p,q); 4 threads per row, 256 cols each (L2-hot) ---
    {
        int rowl = tid >> 2, quarter = tid & 3;
        int row = jbase + rowl;
        int cbase = quarter * 256;
        const float* Lr = Lp + (size_t)row * A + cbase;
        double pq[R] = {0.0, 0.0, 0.0, 0.0};
#pragma unroll 4
        for (int cs = 0; cs < 64; cs++) {
            float4 val = *reinterpret_cast<const float4*>(Lr + cs * 4);
            int col4 = (cbase + cs * 4) * 4;
            {
                double2 pk01 = *reinterpret_cast<const double2*>(&s_pack[swz(col4)]);
                double2 pk23 = *reinterpret_cast<const double2*>(&s_pack[swz(col4 + 2)]);
                double s = splat2(val.x);
                fma2(pq[0], s, pk01.x); fma2(pq[1], s, pk01.y);
                fma2(pq[2], s, pk23.x); fma2(pq[3], s, pk23.y);
            }
            {
                double2 pk01 = *reinterpret_cast<const double2*>(&s_pack[swz(col4 + 4)]);
                double2 pk23 = *reinterpret_cast<const double2*>(&s_pack[swz(col4 + 6)]);
                double s = splat2(val.y);
                fma2(pq[0], s, pk01.x); fma2(pq[1], s, pk01.y);
                fma2(pq[2], s, pk23.x); fma2(pq[3], s, pk23.y);
            }
            {
                double2 pk01 = *reinterpret_cast<const double2*>(&s_pack[swz(col4 + 8)]);
                double2 pk23 = *reinterpret_cast<const double2*>(&s_pack[swz(col4 + 10)]);
                double s = splat2(val.z);
                fma2(pq[0], s, pk01.x); fma2(pq[1], s, pk01.y);
                fma2(pq[2], s, pk23.x); fma2(pq[3], s, pk23.y);
            }
            {
                double2 pk01 = *reinterpret_cast<const double2*>(&s_pack[swz(col4 + 12)]);
                double2 pk23 = *reinterpret_cast<const double2*>(&s_pack[swz(col4 + 14)]);
                double s = splat2(val.w);
                fma2(pq[0], s, pk01.x); fma2(pq[1], s, pk01.y);
                fma2(pq[2], s, pk23.x); fma2(pq[3], s, pk23.y);
            }
        }
#pragma unroll
        for (int r = 0; r < R; r++) {
            pq[r] = add2(pq[r], __shfl_xor_sync(0xffffffffu, pq[r], 1));
            pq[r] = add2(pq[r], __shfl_xor_sync(0xffffffffu, pq[r], 2));
        }
        if (quarter == 0) {
#pragma unroll
            for (int r = 0; r < R; r++) g_PQ[b][r][row] = pq[r];
        }
    }
}

// ============ K7b: reduce UV partials (wide, coalesced) ============
__global__ void __launch_bounds__(512, 1)
k7b_uvred() {
    int idx = blockIdx.x * 512 + threadIdx.x;   // 128 blocks over B*R*A = 65536
    const double* base = &g_UVp[0][0][0][0];
    double s = base[idx];
#pragma unroll
    for (int s16 = 1; s16 < 16; s16++) s = add2(s, base[(size_t)s16 * (B * R * A) + idx]);
    (&g_UV[0][0][0])[idx] = s;
}

// ============ K8: cr softmax + read weights + rv GEMV + output (1 block/b) ====
__global__ void __launch_bounds__(512, 1)
k8_read_out(const float* __restrict__ rw_prev, const float* __restrict__ prec_prev,
            const float* __restrict__ W_rd, const float* __restrict__ b_rd,
            float* __restrict__ out) {
    int b = blockIdx.x;
    int tid = threadIdx.x;  // 512
    __shared__ float s_wr[R][A];
    __shared__ float s_racc[16][R][M];
    __shared__ float s_rv[R * M];
    __shared__ float s_out[2][O_OUT];
    __shared__ float s_pi[R][3];
    __shared__ float s_red[16];

    if (tid < R) {
        float l0 = g_iface[b][OFF_PI + tid * 3 + 0];
        float l1 = g_iface[b][OFF_PI + tid * 3 + 1];
        float l2 = g_iface[b][OFF_PI + tid * 3 + 2];
        float mx = fmaxf(l0, fmaxf(l1, l2));
        float e0 = __expf(l0 - mx), e1 = __expf(l1 - mx), e2 = __expf(l2 - mx);
        float inv = 1.f / (e0 + e1 + e2);
        s_pi[tid][0] = e0 * inv; s_pi[tid][1] = e1 * inv; s_pi[tid][2] = e2 * inv;
    }

#pragma unroll
    for (int r = 0; r < R; r++) {
        float l0 = g_cr[b][r][tid], l1 = g_cr[b][r][tid + 512];
        float mx = blockMax<512>(fmaxf(l0, l1), s_red);
        float e0 = __expf(l0 - mx), e1 = __expf(l1 - mx);
        float s = blockSum<512>(e0 + e1, s_red);
        float inv = 1.f / s;
        s_wr[r][tid] = e0 * inv;
        s_wr[r][tid + 512] = e1 * inv;
    }
    __syncthreads();

    for (int ii = 0; ii < 2; ii++) {
        int a = tid + ii * 512;
        float ww = g_ww[b][a];
        float pp = prec_prev[b * A + a];
#pragma unroll
        for (int r = 0; r < R; r++) {
            float rw = rw_prev[(b * R + r) * A + a];
            float2 PQ = unpack2(g_PQ[b][r][a]);
            float2 UV = unpack2(g_UV[b][r][a]);
            float Sr = g_S[b][r], Tr = g_T[b][r];
            float fwd = (1.f - ww) * PQ.x - PQ.y + ww * (Sr - pp * rw);
            float bwd = (1.f - ww) * UV.x - UV.y + pp * (Tr - ww * rw);
            float cr = s_wr[r][a];
            s_wr[r][a] = s_pi[r][0] * bwd + s_pi[r][1] * cr + s_pi[r][2] * fwd;
        }
    }
    __syncthreads();

    {
        int w = tid >> 5, lane = tid & 31;
        float acc[2][R] = {{0, 0, 0, 0}, {0, 0, 0, 0}};
#pragma unroll 4
        for (int i = 0; i < 64; i++) {
            int a = i * 16 + w;
            float m0 = g_mem[b][a][lane];
            float m1 = g_mem[b][a][lane + 32];
#pragma unroll
            for (int r = 0; r < R; r++) {
                float wr = s_wr[r][a];
                acc[0][r] = fmaf(wr, m0, acc[0][r]);
                acc[1][r] = fmaf(wr, m1, acc[1][r]);
            }
        }
#pragma unroll
        for (int r = 0; r < R; r++) {
            s_racc[w][r][lane] = acc[0][r];
            s_racc[w][r][lane + 32] = acc[1][r];
        }
    }
    __syncthreads();
    if (tid < R * M) {
        float s = 0.f;
#pragma unroll
        for (int w = 0; w < 16; w++) s += s_racc[w][tid >> 6][tid & 63];
        s_rv[tid] = s;
    }
    __syncthreads();

    {
        int half = tid >> 8, col = tid & 255;
        float acc = 0.f;
        const float* W = W_rd + (size_t)half * 128 * O_OUT + col;
#pragma unroll 8
        for (int j = 0; j < 128; j++)
            acc = fmaf(s_rv[half * 128 + j], W[(size_t)j * O_OUT], acc);
        s_out[half][col] = acc;
    }
    __syncthreads();
    if (tid < O_OUT) {
        out[b * O_OUT + tid] = s_out[0][tid] + s_out[1][tid] + g_outhid[b][tid] + b_rd[tid];
    }
}

// ----------------- launch -----------------
extern "C" void kernel_launch(void* const* d_in, const int* in_sizes, int n_in,
                              void* d_out, int out_size) {
    (void)in_sizes; (void)n_in; (void)out_size;
    const float* x          = (const float*)d_in[0];
    const float* h_prev     = (const float*)d_in[1];
    const float* c_prev     = (const float*)d_in[2];
    const float* mem_prev   = (const float*)d_in[3];
    const float* rw_prev    = (const float*)d_in[4];
    const float* ww_prev    = (const float*)d_in[5];
    const float* usage_prev = (const float*)d_in[6];
    const float* prec_prev  = (const float*)d_in[7];
    const float* link_prev  = (const float*)d_in[8];
    const float* rv_prev    = (const float*)d_in[9];
    const float* Wx         = (const float*)d_in[10];
    const float* Wh         = (const float*)d_in[11];
    const float* b_lstm     = (const float*)d_in[12];
    const float* W_hid      = (const float*)d_in[13];
    const float* b_hid      = (const float*)d_in[14];
    const float* W_if       = (const float*)d_in[15];
    const float* b_if       = (const float*)d_in[16];
    const float* W_rd       = (const float*)d_in[17];
    const float* b_rd       = (const float*)d_in[18];
    float* out = (float*)d_out;

    k1_zpart<<<dim3(4, 16), 256>>>(x, h_prev, rv_prev, Wx, Wh);
    k2_lstm<<<64, 128>>>(c_prev, b_lstm);
    k3_iface<<<46, 256>>>(W_if, W_hid, b_if, b_hid);
    k0_usage<<<32, 512>>>(rw_prev, ww_prev, usage_prev);
    k4b_rank<<<dim3(8, B), 256>>>(mem_prev);
    k4c_alloc<<<B, 512>>>(rw_prev, prec_prev);
    k57_mem_link<<<dim3(8, B), 512>>>(mem_prev, link_prev, rw_prev);
    k7b_uvred<<<128, 512>>>();
    k8_read_out<<<B, 512>>>(rw_prev, prec_prev, W_rd, b_rd, out);
}

// round 10
// speedup vs baseline: 1.1164x; 1.0466x over previous
#include <cuda_runtime.h>
#include <math.h>

#define B 16
#define I_IN 256
#define H 512
#define O_OUT 256
#define A 1024
#define M 64
#define R 4
#define IFW 471
#define N4H 2048
#define NCOLS3 (IFW + O_OUT)   // 727

// interface offsets
#define OFF_KR     0
#define OFF_BETAR  256
#define OFF_KW     260
#define OFF_BETAW  324
#define OFF_ERASE  325
#define OFF_WRITEV 389
#define OFF_FREE   453
#define OFF_GA     457
#define OFF_GW     458
#define OFF_PI     459

// ----------------- device scratch -----------------
__device__ float  g_zpart[32][B][N4H];
__device__ float  g_iface[B][IFW];
__device__ float  g_outhid[B][O_OUT];
__device__ float  g_usage[B][A];
__device__ int    g_rank[B][A];
__device__ float  g_cwlog[B][A];
__device__ float  g_ww[B][A];
__device__ float  g_S[B][R];
__device__ float  g_T[B][R];
__device__ float  g_mem[B][A][M];
__device__ float  g_cr[B][R][A];
__device__ double g_PQ[B][R][A];        // packed (p,q)
__device__ double g_UVp[8][B][R][A];    // packed (u,v) partials per stripe

__device__ __forceinline__ float sigf(float x) { return 1.f / (1.f + __expf(-x)); }
__device__ __forceinline__ float oneplusf(float x) {
    return 1.f + (x > 20.f ? x : log1pf(__expf(x)));
}

// packed f32x2 helpers (double as bit-carrier)
__device__ __forceinline__ double pack2(float lo, float hi) {
    double d; asm("mov.b64 %0, {%1,%2};" : "=d"(d) : "f"(lo), "f"(hi)); return d;
}
__device__ __forceinline__ double splat2(float v) {
    double d; asm("mov.b64 %0, {%1,%1};" : "=d"(d) : "f"(v)); return d;
}
__device__ __forceinline__ void fma2(double& acc, double a, double b) {
    asm("fma.rn.f32x2 %0, %1, %2, %3;" : "=d"(acc) : "d"(a), "d"(b), "d"(acc));
}
__device__ __forceinline__ double add2(double a, double b) {
    double d; asm("add.rn.f32x2 %0, %1, %2;" : "=d"(d) : "d"(a), "d"(b)); return d;
}
__device__ __forceinline__ float2 unpack2(double d) {
    float2 f;
    asm("mov.b64 {%0,%1}, %2;" : "=f"(f.x), "=f"(f.y) : "l"(__double_as_longlong(d)));
    return f;
}

// swizzle for pack table (idx = a*4 + r); flips bits [2:4] only
__device__ __forceinline__ int swz(int idx) { return idx ^ (((idx >> 9) & 7) << 2); }

template <int NT>
__device__ __forceinline__ float blockSum(float v, float* s_red) {
    int lane = threadIdx.x & 31, w = threadIdx.x >> 5;
#pragma unroll
    for (int o = 16; o; o >>= 1) v += __shfl_down_sync(0xffffffffu, v, o);
    if (lane == 0) s_red[w] = v;
    __syncthreads();
    if (w == 0) {
        float x = (lane < NT / 32) ? s_red[lane] : 0.f;
#pragma unroll
        for (int o = 16; o; o >>= 1) x += __shfl_down_sync(0xffffffffu, x, o);
        if (lane == 0) s_red[0] = x;
    }
    __syncthreads();
    float res = s_red[0];
    __syncthreads();
    return res;
}
template <int NT>
__device__ __forceinline__ float blockMax(float v, float* s_red) {
    int lane = threadIdx.x & 31, w = threadIdx.x >> 5;
#pragma unroll
    for (int o = 16; o; o >>= 1) v = fmaxf(v, __shfl_down_sync(0xffffffffu, v, o));
    if (lane == 0) s_red[w] = v;
    __syncthreads();
    if (w == 0) {
        float x = (lane < NT / 32) ? s_red[lane] : -1e30f;
#pragma unroll
        for (int o = 16; o; o >>= 1) x = fmaxf(x, __shfl_down_sync(0xffffffffu, x, o));
        if (lane == 0) s_red[0] = x;
    }
    __syncthreads();
    float res = s_red[0];
    __syncthreads();
    return res;
}

// ============ K1: z GEMM, k-split 32 chunks of 32, packed f32x2 (128 blocks) ============
__global__ void __launch_bounds__(256, 1)
k1_zpart(const float* __restrict__ x, const float* __restrict__ h_prev,
         const float* __restrict__ rv_prev, const float* __restrict__ Wx,
         const float* __restrict__ Wh) {
    __shared__ double s_in2[B][32];
    int tid = threadIdx.x;
    int ntile = blockIdx.x;           // 4 tiles of 512 cols
    int kc = blockIdx.y;              // 32 chunks of 32
    int kbase = kc * 32;
    for (int idx = tid; idx < B * 32; idx += 256) {
        int b = idx >> 5, kl = idx & 31;
        int kk = kbase + kl;
        float v;
        if (kk < 256) v = x[b * I_IN + kk];
        else if (kk < 512) v = rv_prev[b * 256 + (kk - 256)];
        else v = h_prev[b * H + (kk - 512)];
        s_in2[b][kl] = splat2(v);
    }
    __syncthreads();
    int n0 = ntile * 512 + tid * 2;
    const float* Wbase = (kbase < 512) ? (Wx + (size_t)kbase * N4H)
                                       : (Wh + (size_t)(kbase - 512) * N4H);
    const char* Wp = (const char*)(Wbase + n0);
    double acc2[B];
#pragma unroll
    for (int b = 0; b < B; b++) acc2[b] = 0.0;
#pragma unroll 4
    for (int kl = 0; kl < 32; kl++) {
        double w2 = *(const double*)(Wp + (size_t)kl * (N4H * 4));
#pragma unroll
        for (int b = 0; b < B; b++) fma2(acc2[b], s_in2[b][kl], w2);
    }
#pragma unroll
    for (int b = 0; b < B; b++)
        *(double*)&g_zpart[kc][b][n0] = acc2[b];
}

// ============ K23: LSTM (z reduce) + iface/out_hidden GEMM, 1 block per b ============
__global__ void __launch_bounds__(736, 1)
k23_lstm_iface(const float* __restrict__ c_prev, const float* __restrict__ b_lstm,
               const float* __restrict__ W_if, const float* __restrict__ W_hid,
               const float* __restrict__ b_if, const float* __restrict__ b_hid) {
    __shared__ float s_h[H];
    int tid = threadIdx.x;
    int b = blockIdx.x;

    if (tid < H) {
        float zv[4];
#pragma unroll
        for (int g = 0; g < 4; g++) {
            int n = g * H + tid;
            float s = b_lstm[n];
#pragma unroll
            for (int kc = 0; kc < 32; kc++) s += g_zpart[kc][b][n];
            zv[g] = s;
        }
        float c = sigf(zv[1]) * c_prev[b * H + tid] + sigf(zv[0]) * tanhf(zv[2]);
        s_h[tid] = sigf(zv[3]) * tanhf(c);
    }
    __syncthreads();

    if (tid < NCOLS3) {
        int col = tid;
        float a0 = 0.f, a1 = 0.f, a2 = 0.f, a3 = 0.f;
        if (col < IFW) {
            const float* W = W_if + col;
#pragma unroll 4
            for (int k = 0; k < H; k += 4) {
                a0 = fmaf(s_h[k],     W[(size_t)(k)     * IFW], a0);
                a1 = fmaf(s_h[k + 1], W[(size_t)(k + 1) * IFW], a1);
                a2 = fmaf(s_h[k + 2], W[(size_t)(k + 2) * IFW], a2);
                a3 = fmaf(s_h[k + 3], W[(size_t)(k + 3) * IFW], a3);
            }
            g_iface[b][col] = (a0 + a1) + (a2 + a3) + b_if[col];
        } else {
            int c2 = col - IFW;
            const float* W = W_hid + c2;
#pragma unroll 4
            for (int k = 0; k < H; k += 4) {
                a0 = fmaf(s_h[k],     W[(size_t)(k)     * O_OUT], a0);
                a1 = fmaf(s_h[k + 1], W[(size_t)(k + 1) * O_OUT], a1);
                a2 = fmaf(s_h[k + 2], W[(size_t)(k + 2) * O_OUT], a2);
                a3 = fmaf(s_h[k + 3], W[(size_t)(k + 3) * O_OUT], a3);
            }
            g_outhid[b][c2] = (a0 + a1) + (a2 + a3) + b_hid[c2];
        }
    }
}

// ============ K4b: usage (in-block) + rank (broadcast scan) + cwlog ============
// grid (8 chunks, B), 256 threads; chunk owns 128 slots/rows
__global__ void __launch_bounds__(256, 1)
k4b_rank(const float* __restrict__ rw_prev, const float* __restrict__ ww_prev,
         const float* __restrict__ usage_prev, const float* __restrict__ mem_prev) {
    __shared__ float s_u[A];
    __shared__ float s_kw[M];
    __shared__ float s_free[R];
    __shared__ float s_bw[1];
    int tid = threadIdx.x;
    int chunk = blockIdx.x, b = blockIdx.y;

    if (tid < R) s_free[tid] = sigf(g_iface[b][OFF_FREE + tid]);
    if (tid < M) s_kw[tid] = g_iface[b][OFF_KW + tid];
    if (tid == 0) s_bw[0] = oneplusf(g_iface[b][OFF_BETAW]);
    __syncthreads();

    // usage for all A (redundant per chunk; cheap)
#pragma unroll
    for (int ii = 0; ii < 4; ii++) {
        int a = tid + ii * 256;
        float psi = 1.f;
#pragma unroll
        for (int r = 0; r < R; r++)
            psi *= (1.f - s_free[r] * rw_prev[(b * R + r) * A + a]);
        float u = usage_prev[b * A + a], w = ww_prev[b * A + a];
        s_u[a] = (u + w - u * w) * psi;
    }
    __syncthreads();
    if (tid < 128) g_usage[b][chunk * 128 + tid] = s_u[chunk * 128 + tid];

    // rank: 2 threads per slot; warp lanes share the scan index -> LDS broadcast
    {
        int slot = chunk * 128 + (tid >> 1);
        int half = tid & 1;
        float u = s_u[slot];
        int cnt = 0;
        int base = half * 512;
#pragma unroll 8
        for (int i = 0; i < 512; i++) {
            float v = s_u[base + i];
            int ia = base + i;
            cnt += (v < u) || (v == u && ia < slot);
        }
        cnt += __shfl_xor_sync(0xffffffffu, cnt, 1);
        if (half == 0) g_rank[b][slot] = cnt;
    }

    // cwlog: 2 threads per row, each 32 floats (8 float4)
    {
        int row = chunk * 128 + (tid >> 1);
        int half = tid & 1;
        const float4* mrow =
            reinterpret_cast<const float4*>(mem_prev + ((size_t)(b * A + row)) * M) + half * 8;
        float d = 0.f, n = 0.f;
#pragma unroll
        for (int q = 0; q < 8; q++) {
            float4 v = mrow[q];
            int m0 = half * 32 + q * 4;
            d += v.x * s_kw[m0] + v.y * s_kw[m0 + 1] + v.z * s_kw[m0 + 2] + v.w * s_kw[m0 + 3];
            n += v.x * v.x + v.y * v.y + v.z * v.z + v.w * v.w;
        }
        d += __shfl_xor_sync(0xffffffffu, d, 1);
        n += __shfl_xor_sync(0xffffffffu, n, 1);
        if (half == 0) {
            float kn2 = 0.f;
#pragma unroll
            for (int m = 0; m < M; m++) { float v = s_kw[m]; kn2 = fmaf(v, v, kn2); }
            g_cwlog[b][row] = s_bw[0] * d / (sqrtf(kn2) * sqrtf(n) + 1e-6f);
        }
    }
}

// ============ K4c: scatter + cumprod + alloc + cw softmax + ww + S,T ============
__global__ void __launch_bounds__(512, 1)
k4c_alloc(const float* __restrict__ rw_prev, const float* __restrict__ prec_prev) {
    int b = blockIdx.x;
    int tid = threadIdx.x;  // 512
    __shared__ float s_sorted[A];
    __shared__ float s_tmp[A];
    __shared__ float s_cw[A];
    __shared__ float s_red[16];
    __shared__ float s_scal[4];

    if (tid == 0) {
        s_scal[0] = sigf(g_iface[b][OFF_GA]);
        s_scal[1] = sigf(g_iface[b][OFF_GW]);
    }

    float u0 = g_usage[b][tid], u1 = g_usage[b][tid + 512];
    int r0 = g_rank[b][tid], r1 = g_rank[b][tid + 512];
    s_sorted[r0] = u0;
    s_sorted[r1] = u1;
    __syncthreads();

    // inclusive cumprod (Hillis-Steele, 10 steps)
    float* src = s_sorted;
    float* dst = s_tmp;
    for (int off = 1; off < A; off <<= 1) {
        for (int i = tid; i < A; i += 512)
            dst[i] = (i >= off) ? src[i - off] * src[i] : src[i];
        __syncthreads();
        float* t = src; src = dst; dst = t;
    }
    float alloc0 = (1.f - u0) * (r0 == 0 ? 1.f : src[r0 - 1]);
    float alloc1 = (1.f - u1) * (r1 == 0 ? 1.f : src[r1 - 1]);

    // c_w softmax
    float l0 = g_cwlog[b][tid], l1 = g_cwlog[b][tid + 512];
    float mx = blockMax<512>(fmaxf(l0, l1), s_red);
    float e0 = __expf(l0 - mx), e1 = __expf(l1 - mx);
    float ssum = blockSum<512>(e0 + e1, s_red);
    float inv = 1.f / ssum;
    s_cw[tid] = e0 * inv;
    s_cw[tid + 512] = e1 * inv;
    __syncthreads();

    float ga = s_scal[0], gw = s_scal[1];
    float sS[R] = {0, 0, 0, 0}, sT[R] = {0, 0, 0, 0};
    float wwv0 = gw * (ga * alloc0 + (1.f - ga) * s_cw[tid]);
    float wwv1 = gw * (ga * alloc1 + (1.f - ga) * s_cw[tid + 512]);
    g_ww[b][tid] = wwv0;
    g_ww[b][tid + 512] = wwv1;
    {
        float pp0 = prec_prev[b * A + tid], pp1 = prec_prev[b * A + tid + 512];
#pragma unroll
        for (int r = 0; r < R; r++) {
            float rw0 = rw_prev[(b * R + r) * A + tid];
            float rw1 = rw_prev[(b * R + r) * A + tid + 512];
            sS[r] = fmaf(pp0, rw0, fmaf(pp1, rw1, sS[r]));
            sT[r] = fmaf(wwv0, rw0, fmaf(wwv1, rw1, sT[r]));
        }
    }
#pragma unroll
    for (int r = 0; r < R; r++) {
        float v = blockSum<512>(sS[r], s_red);
        if (tid == 0) g_S[b][r] = v;
        v = blockSum<512>(sT[r], s_red);
        if (tid == 0) g_T[b][r] = v;
    }
}

// ============ K57: mem write + c_r logits + link pass ============
__global__ void __launch_bounds__(512, 1)
k57_mem_link(const float* __restrict__ mem_prev, const float* __restrict__ link_prev,
             const float* __restrict__ rw_prev) {
    __shared__ double s_pack[A * 4];          // 32 KB
    __shared__ float  s_kr[R][M];
    __shared__ float  s_er[M], s_wv[M];
    __shared__ float  s_beta[R], s_kn[R];
    int tid = threadIdx.x;                    // 512
    int stripe = blockIdx.x;                  // 8 stripes of 128 rows
    int b = blockIdx.y;
    int jbase = stripe * 128;

    // --- params ---
    if (tid < 256) {
        int r = tid >> 6, m = tid & 63;
        s_kr[r][m] = g_iface[b][OFF_KR + r * M + m];
    } else if (tid < 256 + M) {
        s_er[tid - 256] = sigf(g_iface[b][OFF_ERASE + (tid - 256)]);
    } else if (tid < 256 + 2 * M) {
        s_wv[tid - 256 - M] = g_iface[b][OFF_WRITEV + (tid - 256 - M)];
    }
    __syncthreads();
    if (tid < R) {
        s_beta[tid] = oneplusf(g_iface[b][OFF_BETAR + tid]);
        float s = 0.f;
#pragma unroll
        for (int m = 0; m < M; m++) { float v = s_kr[tid][m]; s = fmaf(v, v, s); }
        s_kn[tid] = sqrtf(s);
    }
    __syncthreads();

    // --- part 1: mem update + cr logits for rows [jbase, jbase+128) ---
    {
        int lane16 = tid & 15, m0 = lane16 * 4;
#pragma unroll
        for (int pass = 0; pass < 4; pass++) {
            int a = jbase + pass * 32 + (tid >> 4);
            float w = g_ww[b][a];
            float4 v = *reinterpret_cast<const float4*>(mem_prev + ((size_t)(b * A + a)) * M + m0);
            float n0 = v.x * (1.f - w * s_er[m0])     + w * s_wv[m0];
            float n1 = v.y * (1.f - w * s_er[m0 + 1]) + w * s_wv[m0 + 1];
            float n2 = v.z * (1.f - w * s_er[m0 + 2]) + w * s_wv[m0 + 2];
            float n3 = v.w * (1.f - w * s_er[m0 + 3]) + w * s_wv[m0 + 3];
            *reinterpret_cast<float4*>(&g_mem[b][a][m0]) = make_float4(n0, n1, n2, n3);
            float nn = n0 * n0 + n1 * n1 + n2 * n2 + n3 * n3;
            float d[R];
#pragma unroll
            for (int r = 0; r < R; r++)
                d[r] = n0 * s_kr[r][m0] + n1 * s_kr[r][m0 + 1] +
                       n2 * s_kr[r][m0 + 2] + n3 * s_kr[r][m0 + 3];
#pragma unroll
            for (int o = 8; o; o >>= 1) {
                nn += __shfl_xor_sync(0xffffffffu, nn, o);
#pragma unroll
                for (int r = 0; r < R; r++) d[r] += __shfl_xor_sync(0xffffffffu, d[r], o);
            }
            if (lane16 == 0) {
                float mn = sqrtf(nn);
#pragma unroll
                for (int r = 0; r < R; r++)
                    g_cr[b][r][a] = s_beta[r] * d[r] / (s_kn[r] * mn + 1e-6f);
            }
        }
    }

    // --- pack table ---
    for (int a = tid; a < A; a += 512) {
        float w = g_ww[b][a];
#pragma unroll
        for (int r = 0; r < R; r++) {
            float rw = rw_prev[(b * R + r) * A + a];
            s_pack[swz(a * 4 + r)] = pack2(rw, w * rw);
        }
    }
    __syncthreads();

    const float* Lp = link_prev + (size_t)b * A * A;

    // --- phase A: column partials (u,v); thread owns 2 cols, full 128 rows ---
    {
        int col2 = 2 * tid;  // 0..1022
        double uv0[R], uv1[R];
#pragma unroll
        for (int r = 0; r < R; r++) { uv0[r] = 0.0; uv1[r] = 0.0; }
#pragma unroll 4
        for (int j = 0; j < 128; j++) {
            int row = jbase + j;
            float2 val = *reinterpret_cast<const float2*>(Lp + (size_t)row * A + col2);
            int j4 = row * 4;
            double2 pk01 = *reinterpret_cast<const double2*>(&s_pack[swz(j4)]);
            double2 pk23 = *reinterpret_cast<const double2*>(&s_pack[swz(j4 + 2)]);
            double sx = splat2(val.x), sy = splat2(val.y);
            fma2(uv0[0], sx, pk01.x); fma2(uv0[1], sx, pk01.y);
            fma2(uv0[2], sx, pk23.x); fma2(uv0[3], sx, pk23.y);
            fma2(uv1[0], sy, pk01.x); fma2(uv1[1], sy, pk01.y);
            fma2(uv1[2], sy, pk23.x); fma2(uv1[3], sy, pk23.y);
        }
#pragma unroll
        for (int r = 0; r < R; r++) {
            double2 st; st.x = uv0[r]; st.y = uv1[r];
            *reinterpret_cast<double2*>(&g_UVp[stripe][b][r][col2]) = st;
        }
    }

    // --- phase B: row dots (p,q); 4 threads per row, 256 cols each (L2-hot) ---
    {
        int rowl = tid >> 2, quarter = tid & 3;
        int row = jbase + rowl;
        int cbase = quarter * 256;
        const float* Lr = Lp + (size_t)row * A + cbase;
        double pq[R] = {0.0, 0.0, 0.0, 0.0};
#pragma unroll 4
        for (int cs = 0; cs < 64; cs++) {
            float4 val = *reinterpret_cast<const float4*>(Lr + cs * 4);
            int col4 = (cbase + cs * 4) * 4;
            {
                double2 pk01 = *reinterpret_cast<const double2*>(&s_pack[swz(col4)]);
                double2 pk23 = *reinterpret_cast<const double2*>(&s_pack[swz(col4 + 2)]);
                double s = splat2(val.x);
                fma2(pq[0], s, pk01.x); fma2(pq[1], s, pk01.y);
                fma2(pq[2], s, pk23.x); fma2(pq[3], s, pk23.y);
            }
            {
                double2 pk01 = *reinterpret_cast<const double2*>(&s_pack[swz(col4 + 4)]);
                double2 pk23 = *reinterpret_cast<const double2*>(&s_pack[swz(col4 + 6)]);
                double s = splat2(val.y);
                fma2(pq[0], s, pk01.x); fma2(pq[1], s, pk01.y);
                fma2(pq[2], s, pk23.x); fma2(pq[3], s, pk23.y);
            }
            {
                double2 pk01 = *reinterpret_cast<const double2*>(&s_pack[swz(col4 + 8)]);
                double2 pk23 = *reinterpret_cast<const double2*>(&s_pack[swz(col4 + 10)]);
                double s = splat2(val.z);
                fma2(pq[0], s, pk01.x); fma2(pq[1], s, pk01.y);
                fma2(pq[2], s, pk23.x); fma2(pq[3], s, pk23.y);
            }
            {
                double2 pk01 = *reinterpret_cast<const double2*>(&s_pack[swz(col4 + 12)]);
                double2 pk23 = *reinterpret_cast<const double2*>(&s_pack[swz(col4 + 14)]);
                double s = splat2(val.w);
                fma2(pq[0], s, pk01.x); fma2(pq[1], s, pk01.y);
                fma2(pq[2], s, pk23.x); fma2(pq[3], s, pk23.y);
            }
        }
#pragma unroll
        for (int r = 0; r < R; r++) {
            pq[r] = add2(pq[r], __shfl_xor_sync(0xffffffffu, pq[r], 1));
            pq[r] = add2(pq[r], __shfl_xor_sync(0xffffffffu, pq[r], 2));
        }
        if (quarter == 0) {
#pragma unroll
            for (int r = 0; r < R; r++) g_PQ[b][r][row] = pq[r];
        }
    }
}

// ============ K8: UV reduce + cr softmax + read weights + rv GEMV + output ====
__global__ void __launch_bounds__(512, 1)
k8_read_out(const float* __restrict__ rw_prev, const float* __restrict__ prec_prev,
            const float* __restrict__ W_rd, const float* __restrict__ b_rd,
            float* __restrict__ out) {
    int b = blockIdx.x;
    int tid = threadIdx.x;  // 512
    __shared__ float s_wr[R][A];
    __shared__ float s_racc[16][R][M];
    __shared__ float s_rv[R * M];
    __shared__ float s_out[2][O_OUT];
    __shared__ float s_pi[R][3];
    __shared__ float s_red[16];

    if (tid < R) {
        float l0 = g_iface[b][OFF_PI + tid * 3 + 0];
        float l1 = g_iface[b][OFF_PI + tid * 3 + 1];
        float l2 = g_iface[b][OFF_PI + tid * 3 + 2];
        float mx = fmaxf(l0, fmaxf(l1, l2));
        float e0 = __expf(l0 - mx), e1 = __expf(l1 - mx), e2 = __expf(l2 - mx);
        float inv = 1.f / (e0 + e1 + e2);
        s_pi[tid][0] = e0 * inv; s_pi[tid][1] = e1 * inv; s_pi[tid][2] = e2 * inv;
    }

#pragma unroll
    for (int r = 0; r < R; r++) {
        float l0 = g_cr[b][r][tid], l1 = g_cr[b][r][tid + 512];
        float mx = blockMax<512>(fmaxf(l0, l1), s_red);
        float e0 = __expf(l0 - mx), e1 = __expf(l1 - mx);
        float s = blockSum<512>(e0 + e1, s_red);
        float inv = 1.f / s;
        s_wr[r][tid] = e0 * inv;
        s_wr[r][tid + 512] = e1 * inv;
    }
    __syncthreads();

    for (int ii = 0; ii < 2; ii++) {
        int a = tid + ii * 512;
        float ww = g_ww[b][a];
        float pp = prec_prev[b * A + a];
#pragma unroll
        for (int r = 0; r < R; r++) {
            float rw = rw_prev[(b * R + r) * A + a];
            float2 PQ = unpack2(g_PQ[b][r][a]);
            double uvs = g_UVp[0][b][r][a];
#pragma unroll
            for (int s8 = 1; s8 < 8; s8++) uvs = add2(uvs, g_UVp[s8][b][r][a]);
            float2 UV = unpack2(uvs);
            float Sr = g_S[b][r], Tr = g_T[b][r];
            float fwd = (1.f - ww) * PQ.x - PQ.y + ww * (Sr - pp * rw);
            float bwd = (1.f - ww) * UV.x - UV.y + pp * (Tr - ww * rw);
            float cr = s_wr[r][a];
            s_wr[r][a] = s_pi[r][0] * bwd + s_pi[r][1] * cr + s_pi[r][2] * fwd;
        }
    }
    __syncthreads();

    {
        int w = tid >> 5, lane = tid & 31;
        float acc[2][R] = {{0, 0, 0, 0}, {0, 0, 0, 0}};
#pragma unroll 4
        for (int i = 0; i < 64; i++) {
            int a = i * 16 + w;
            float m0 = g_mem[b][a][lane];
            float m1 = g_mem[b][a][lane + 32];
#pragma unroll
            for (int r = 0; r < R; r++) {
                float wr = s_wr[r][a];
                acc[0][r] = fmaf(wr, m0, acc[0][r]);
                acc[1][r] = fmaf(wr, m1, acc[1][r]);
            }
        }
#pragma unroll
        for (int r = 0; r < R; r++) {
            s_racc[w][r][lane] = acc[0][r];
            s_racc[w][r][lane + 32] = acc[1][r];
        }
    }
    __syncthreads();
    if (tid < R * M) {
        float s = 0.f;
#pragma unroll
        for (int w = 0; w < 16; w++) s += s_racc[w][tid >> 6][tid & 63];
        s_rv[tid] = s;
    }
    __syncthreads();

    {
        int half = tid >> 8, col = tid & 255;
        float acc = 0.f;
        const float* W = W_rd + (size_t)half * 128 * O_OUT + col;
#pragma unroll 8
        for (int j = 0; j < 128; j++)
            acc = fmaf(s_rv[half * 128 + j], W[(size_t)j * O_OUT], acc);
        s_out[half][col] = acc;
    }
    __syncthreads();
    if (tid < O_OUT) {
        out[b * O_OUT + tid] = s_out[0][tid] + s_out[1][tid] + g_outhid[b][tid] + b_rd[tid];
    }
}

// ----------------- launch -----------------
extern "C" void kernel_launch(void* const* d_in, const int* in_sizes, int n_in,
                              void* d_out, int out_size) {
    (void)in_sizes; (void)n_in; (void)out_size;
    const float* x          = (const float*)d_in[0];
    const float* h_prev     = (const float*)d_in[1];
    const float* c_prev     = (const float*)d_in[2];
    const float* mem_prev   = (const float*)d_in[3];
    const float* rw_prev    = (const float*)d_in[4];
    const float* ww_prev    = (const float*)d_in[5];
    const float* usage_prev = (const float*)d_in[6];
    const float* prec_prev  = (const float*)d_in[7];
    const float* link_prev  = (const float*)d_in[8];
    const float* rv_prev    = (const float*)d_in[9];
    const float* Wx         = (const float*)d_in[10];
    const float* Wh         = (const float*)d_in[11];
    const float* b_lstm     = (const float*)d_in[12];
    const float* W_hid      = (const float*)d_in[13];
    const float* b_hid      = (const float*)d_in[14];
    const float* W_if       = (const float*)d_in[15];
    const float* b_if       = (const float*)d_in[16];
    const float* W_rd       = (const float*)d_in[17];
    const float* b_rd       = (const float*)d_in[18];
    float* out = (float*)d_out;

    k1_zpart<<<dim3(4, 32), 256>>>(x, h_prev, rv_prev, Wx, Wh);
    k23_lstm_iface<<<B, 736>>>(c_prev, b_lstm, W_if, W_hid, b_if, b_hid);
    k4b_rank<<<dim3(8, B), 256>>>(rw_prev, ww_prev, usage_prev, mem_prev);
    k4c_alloc<<<B, 512>>>(rw_prev, prec_prev);
    k57_mem_link<<<dim3(8, B), 512>>>(mem_prev, link_prev, rw_prev);
    k8_read_out<<<B, 512>>>(rw_prev, prec_prev, W_rd, b_rd, out);
}

// round 11
// speedup vs baseline: 1.1525x; 1.0323x over previous
#include <cuda_runtime.h>
#include <math.h>

#define B 16
#define I_IN 256
#define H 512
#define O_OUT 256
#define A 1024
#define M 64
#define R 4
#define IFW 471
#define N4H 2048
#define NCOLS3 (IFW + O_OUT)   // 727

// interface offsets
#define OFF_KR     0
#define OFF_BETAR  256
#define OFF_KW     260
#define OFF_BETAW  324
#define OFF_ERASE  325
#define OFF_WRITEV 389
#define OFF_FREE   453
#define OFF_GA     457
#define OFF_GW     458
#define OFF_PI     459

// ----------------- device scratch -----------------
__device__ float  g_zpart[32][B][N4H];
__device__ float  g_iface[B][IFW];
__device__ float  g_outhid[B][O_OUT];
__device__ float  g_usage[B][A];
__device__ int    g_rank[B][A];
__device__ float  g_cwlog[B][A];
__device__ float  g_ww[B][A];
__device__ float  g_S[B][R];
__device__ float  g_T[B][R];
__device__ float  g_mem[B][A][M];
__device__ float  g_cr[B][R][A];
__device__ double g_PQ[B][R][A];        // packed (p,q)
__device__ double g_UVp[8][B][R][A];    // packed (u,v) partials per stripe

__device__ __forceinline__ float sigf(float x) { return 1.f / (1.f + __expf(-x)); }
__device__ __forceinline__ float oneplusf(float x) {
    return 1.f + (x > 20.f ? x : log1pf(__expf(x)));
}

// packed f32x2 helpers (double as bit-carrier)
__device__ __forceinline__ double pack2(float lo, float hi) {
    double d; asm("mov.b64 %0, {%1,%2};" : "=d"(d) : "f"(lo), "f"(hi)); return d;
}
__device__ __forceinline__ double splat2(float v) {
    double d; asm("mov.b64 %0, {%1,%1};" : "=d"(d) : "f"(v)); return d;
}
__device__ __forceinline__ void fma2(double& acc, double a, double b) {
    asm("fma.rn.f32x2 %0, %1, %2, %3;" : "=d"(acc) : "d"(a), "d"(b), "d"(acc));
}
__device__ __forceinline__ double add2(double a, double b) {
    double d; asm("add.rn.f32x2 %0, %1, %2;" : "=d"(d) : "d"(a), "d"(b)); return d;
}
__device__ __forceinline__ float2 unpack2(double d) {
    float2 f;
    asm("mov.b64 {%0,%1}, %2;" : "=f"(f.x), "=f"(f.y) : "l"(__double_as_longlong(d)));
    return f;
}

// swizzle for pack table (idx = a*4 + r); flips bits [2:4] only
__device__ __forceinline__ int swz(int idx) { return idx ^ (((idx >> 9) & 7) << 2); }

template <int NT>
__device__ __forceinline__ float blockSum(float v, float* s_red) {
    int lane = threadIdx.x & 31, w = threadIdx.x >> 5;
#pragma unroll
    for (int o = 16; o; o >>= 1) v += __shfl_down_sync(0xffffffffu, v, o);
    if (lane == 0) s_red[w] = v;
    __syncthreads();
    if (w == 0) {
        float x = (lane < NT / 32) ? s_red[lane] : 0.f;
#pragma unroll
        for (int o = 16; o; o >>= 1) x += __shfl_down_sync(0xffffffffu, x, o);
        if (lane == 0) s_red[0] = x;
    }
    __syncthreads();
    float res = s_red[0];
    __syncthreads();
    return res;
}
template <int NT>
__device__ __forceinline__ float blockMax(float v, float* s_red) {
    int lane = threadIdx.x & 31, w = threadIdx.x >> 5;
#pragma unroll
    for (int o = 16; o; o >>= 1) v = fmaxf(v, __shfl_down_sync(0xffffffffu, v, o));
    if (lane == 0) s_red[w] = v;
    __syncthreads();
    if (w == 0) {
        float x = (lane < NT / 32) ? s_red[lane] : -1e30f;
#pragma unroll
        for (int o = 16; o; o >>= 1) x = fmaxf(x, __shfl_down_sync(0xffffffffu, x, o));
        if (lane == 0) s_red[0] = x;
    }
    __syncthreads();
    float res = s_red[0];
    __syncthreads();
    return res;
}

// ============ K1: z GEMM, k-split 32 chunks of 32, packed f32x2 (128 blocks) ============
__global__ void __launch_bounds__(256, 1)
k1_zpart(const float* __restrict__ x, const float* __restrict__ h_prev,
         const float* __restrict__ rv_prev, const float* __restrict__ Wx,
         const float* __restrict__ Wh) {
    __shared__ double s_in2[B][32];
    int tid = threadIdx.x;
    int ntile = blockIdx.x;
    int kc = blockIdx.y;
    int kbase = kc * 32;
    for (int idx = tid; idx < B * 32; idx += 256) {
        int b = idx >> 5, kl = idx & 31;
        int kk = kbase + kl;
        float v;
        if (kk < 256) v = x[b * I_IN + kk];
        else if (kk < 512) v = rv_prev[b * 256 + (kk - 256)];
        else v = h_prev[b * H + (kk - 512)];
        s_in2[b][kl] = splat2(v);
    }
    __syncthreads();
    int n0 = ntile * 512 + tid * 2;
    const float* Wbase = (kbase < 512) ? (Wx + (size_t)kbase * N4H)
                                       : (Wh + (size_t)(kbase - 512) * N4H);
    const char* Wp = (const char*)(Wbase + n0);
    double acc2[B];
#pragma unroll
    for (int b = 0; b < B; b++) acc2[b] = 0.0;
#pragma unroll 4
    for (int kl = 0; kl < 32; kl++) {
        double w2 = *(const double*)(Wp + (size_t)kl * (N4H * 4));
#pragma unroll
        for (int b = 0; b < B; b++) fma2(acc2[b], s_in2[b][kl], w2);
    }
#pragma unroll
    for (int b = 0; b < B; b++)
        *(double*)&g_zpart[kc][b][n0] = acc2[b];
}

// ============ K23: LSTM (z reduce) + iface/out_hidden GEMM, grid (2, B) ============
__global__ void __launch_bounds__(736, 1)
k23_lstm_iface(const float* __restrict__ c_prev, const float* __restrict__ b_lstm,
               const float* __restrict__ W_if, const float* __restrict__ W_hid,
               const float* __restrict__ b_if, const float* __restrict__ b_hid) {
    __shared__ float s_h[H];
    int tid = threadIdx.x;
    int half = blockIdx.x;   // 0 or 1
    int b = blockIdx.y;

    if (tid < H) {
        float zv[4];
#pragma unroll
        for (int g = 0; g < 4; g++) {
            int n = g * H + tid;
            float s = b_lstm[n];
#pragma unroll
            for (int kc = 0; kc < 32; kc++) s += g_zpart[kc][b][n];
            zv[g] = s;
        }
        float c = sigf(zv[1]) * c_prev[b * H + tid] + sigf(zv[0]) * tanhf(zv[2]);
        s_h[tid] = sigf(zv[3]) * tanhf(c);
    }
    __syncthreads();

    int col = half * 368 + tid;
    if (tid < 368 && col < NCOLS3) {
        float a0 = 0.f, a1 = 0.f, a2 = 0.f, a3 = 0.f;
        if (col < IFW) {
            const float* W = W_if + col;
#pragma unroll 4
            for (int k = 0; k < H; k += 4) {
                a0 = fmaf(s_h[k],     W[(size_t)(k)     * IFW], a0);
                a1 = fmaf(s_h[k + 1], W[(size_t)(k + 1) * IFW], a1);
                a2 = fmaf(s_h[k + 2], W[(size_t)(k + 2) * IFW], a2);
                a3 = fmaf(s_h[k + 3], W[(size_t)(k + 3) * IFW], a3);
            }
            g_iface[b][col] = (a0 + a1) + (a2 + a3) + b_if[col];
        } else {
            int c2 = col - IFW;
            const float* W = W_hid + c2;
#pragma unroll 4
            for (int k = 0; k < H; k += 4) {
                a0 = fmaf(s_h[k],     W[(size_t)(k)     * O_OUT], a0);
                a1 = fmaf(s_h[k + 1], W[(size_t)(k + 1) * O_OUT], a1);
                a2 = fmaf(s_h[k + 2], W[(size_t)(k + 2) * O_OUT], a2);
                a3 = fmaf(s_h[k + 3], W[(size_t)(k + 3) * O_OUT], a3);
            }
            g_outhid[b][c2] = (a0 + a1) + (a2 + a3) + b_hid[c2];
        }
    }
}

// ============ K4b: usage (in-block) + rank (broadcast scan) + cwlog ============
// grid (8 chunks, B), 256 threads; chunk owns 128 slots/rows
__global__ void __launch_bounds__(256, 1)
k4b_rank(const float* __restrict__ rw_prev, const float* __restrict__ ww_prev,
         const float* __restrict__ usage_prev, const float* __restrict__ mem_prev) {
    __shared__ float s_u[A];
    __shared__ float s_kw[M];
    __shared__ float s_free[R];
    __shared__ float s_bw[1];
    int tid = threadIdx.x;
    int chunk = blockIdx.x, b = blockIdx.y;

    if (tid < R) s_free[tid] = sigf(g_iface[b][OFF_FREE + tid]);
    if (tid < M) s_kw[tid] = g_iface[b][OFF_KW + tid];
    if (tid == 0) s_bw[0] = oneplusf(g_iface[b][OFF_BETAW]);
    __syncthreads();

#pragma unroll
    for (int ii = 0; ii < 4; ii++) {
        int a = tid + ii * 256;
        float psi = 1.f;
#pragma unroll
        for (int r = 0; r < R; r++)
            psi *= (1.f - s_free[r] * rw_prev[(b * R + r) * A + a]);
        float u = usage_prev[b * A + a], w = ww_prev[b * A + a];
        s_u[a] = (u + w - u * w) * psi;
    }
    __syncthreads();
    if (tid < 128) g_usage[b][chunk * 128 + tid] = s_u[chunk * 128 + tid];

    // rank: 2 threads per slot; warp lanes share the scan index -> LDS broadcast
    {
        int slot = chunk * 128 + (tid >> 1);
        int half = tid & 1;
        float u = s_u[slot];
        int cnt = 0;
        int base = half * 512;
#pragma unroll 8
        for (int i = 0; i < 512; i++) {
            float v = s_u[base + i];
            int ia = base + i;
            cnt += (v < u) || (v == u && ia < slot);
        }
        cnt += __shfl_xor_sync(0xffffffffu, cnt, 1);
        if (half == 0) g_rank[b][slot] = cnt;
    }

    // cwlog: 2 threads per row, each 32 floats (8 float4)
    {
        int row = chunk * 128 + (tid >> 1);
        int half = tid & 1;
        const float4* mrow =
            reinterpret_cast<const float4*>(mem_prev + ((size_t)(b * A + row)) * M) + half * 8;
        float d = 0.f, n = 0.f;
#pragma unroll
        for (int q = 0; q < 8; q++) {
            float4 v = mrow[q];
            int m0 = half * 32 + q * 4;
            d += v.x * s_kw[m0] + v.y * s_kw[m0 + 1] + v.z * s_kw[m0 + 2] + v.w * s_kw[m0 + 3];
            n += v.x * v.x + v.y * v.y + v.z * v.z + v.w * v.w;
        }
        d += __shfl_xor_sync(0xffffffffu, d, 1);
        n += __shfl_xor_sync(0xffffffffu, n, 1);
        if (half == 0) {
            float kn2 = 0.f;
#pragma unroll
            for (int m = 0; m < M; m++) { float v = s_kw[m]; kn2 = fmaf(v, v, kn2); }
            g_cwlog[b][row] = s_bw[0] * d / (sqrtf(kn2) * sqrtf(n) + 1e-6f);
        }
    }
}

// ============ K57: alloc/ww (inline, redundant) + mem write + c_r + link pass ============
__global__ void __launch_bounds__(512, 1)
k57_mem_link(const float* __restrict__ mem_prev, const float* __restrict__ link_prev,
             const float* __restrict__ rw_prev, const float* __restrict__ prec_prev) {
    __shared__ double s_pack[A * 4];          // 32 KB; first 8 KB overlaid by cumprod scratch
    __shared__ float  s_ww[A];
    __shared__ float  s_kr[R][M];
    __shared__ float  s_er[M], s_wv[M];
    __shared__ float  s_beta[R], s_kn[R];
    __shared__ float  s_red[16];
    int tid = threadIdx.x;                    // 512
    int stripe = blockIdx.x;                  // 8 stripes of 128 rows
    int b = blockIdx.y;
    int jbase = stripe * 128;

    float* s_sorted = (float*)s_pack;         // [A]
    float* s_tmp = ((float*)s_pack) + A;      // [A]

    // --- params ---
    if (tid < 256) {
        int r = tid >> 6, m = tid & 63;
        s_kr[r][m] = g_iface[b][OFF_KR + r * M + m];
    } else if (tid < 256 + M) {
        s_er[tid - 256] = sigf(g_iface[b][OFF_ERASE + (tid - 256)]);
    } else if (tid < 256 + 2 * M) {
        s_wv[tid - 256 - M] = g_iface[b][OFF_WRITEV + (tid - 256 - M)];
    }
    __syncthreads();
    if (tid < R) {
        s_beta[tid] = oneplusf(g_iface[b][OFF_BETAR + tid]);
        float s = 0.f;
#pragma unroll
        for (int m = 0; m < M; m++) { float v = s_kr[tid][m]; s = fmaf(v, v, s); }
        s_kn[tid] = sqrtf(s);
    }

    // --- alloc + ww (redundant per block; removes the k4c kernel) ---
    float u0 = g_usage[b][tid], u1 = g_usage[b][tid + 512];
    int r0 = g_rank[b][tid], r1 = g_rank[b][tid + 512];
    s_sorted[r0] = u0;
    s_sorted[r1] = u1;
    __syncthreads();
    {
        float* src = s_sorted;
        float* dst = s_tmp;
        for (int off = 1; off < A; off <<= 1) {
            for (int i = tid; i < A; i += 512)
                dst[i] = (i >= off) ? src[i - off] * src[i] : src[i];
            __syncthreads();
            float* t = src; src = dst; dst = t;
        }
        float alloc0 = (1.f - u0) * (r0 == 0 ? 1.f : src[r0 - 1]);
        float alloc1 = (1.f - u1) * (r1 == 0 ? 1.f : src[r1 - 1]);

        // c_w softmax (register-resident)
        float l0 = g_cwlog[b][tid], l1 = g_cwlog[b][tid + 512];
        float mx = blockMax<512>(fmaxf(l0, l1), s_red);
        float e0 = __expf(l0 - mx), e1 = __expf(l1 - mx);
        float ssum = blockSum<512>(e0 + e1, s_red);
        float inv = 1.f / ssum;

        float ga = sigf(g_iface[b][OFF_GA]), gw = sigf(g_iface[b][OFF_GW]);
        float wwv0 = gw * (ga * alloc0 + (1.f - ga) * e0 * inv);
        float wwv1 = gw * (ga * alloc1 + (1.f - ga) * e1 * inv);
        s_ww[tid] = wwv0;
        s_ww[tid + 512] = wwv1;

        if (stripe == 0) {
            g_ww[b][tid] = wwv0;
            g_ww[b][tid + 512] = wwv1;
            float pp0 = prec_prev[b * A + tid], pp1 = prec_prev[b * A + tid + 512];
            float sS[R], sT[R];
#pragma unroll
            for (int r = 0; r < R; r++) {
                float rw0 = rw_prev[(b * R + r) * A + tid];
                float rw1 = rw_prev[(b * R + r) * A + tid + 512];
                sS[r] = fmaf(pp0, rw0, pp1 * rw1);
                sT[r] = fmaf(wwv0, rw0, wwv1 * rw1);
            }
#pragma unroll
            for (int r = 0; r < R; r++) {
                float v = blockSum<512>(sS[r], s_red);
                if (tid == 0) g_S[b][r] = v;
                v = blockSum<512>(sT[r], s_red);
                if (tid == 0) g_T[b][r] = v;
            }
        }
    }
    __syncthreads();

    // --- part 1: mem update + cr logits for rows [jbase, jbase+128) ---
    {
        int lane16 = tid & 15, m0 = lane16 * 4;
#pragma unroll
        for (int pass = 0; pass < 4; pass++) {
            int a = jbase + pass * 32 + (tid >> 4);
            float w = s_ww[a];
            float4 v = *reinterpret_cast<const float4*>(mem_prev + ((size_t)(b * A + a)) * M + m0);
            float n0 = v.x * (1.f - w * s_er[m0])     + w * s_wv[m0];
            float n1 = v.y * (1.f - w * s_er[m0 + 1]) + w * s_wv[m0 + 1];
            float n2 = v.z * (1.f - w * s_er[m0 + 2]) + w * s_wv[m0 + 2];
            float n3 = v.w * (1.f - w * s_er[m0 + 3]) + w * s_wv[m0 + 3];
            *reinterpret_cast<float4*>(&g_mem[b][a][m0]) = make_float4(n0, n1, n2, n3);
            float nn = n0 * n0 + n1 * n1 + n2 * n2 + n3 * n3;
            float d[R];
#pragma unroll
            for (int r = 0; r < R; r++)
                d[r] = n0 * s_kr[r][m0] + n1 * s_kr[r][m0 + 1] +
                       n2 * s_kr[r][m0 + 2] + n3 * s_kr[r][m0 + 3];
#pragma unroll
            for (int o = 8; o; o >>= 1) {
                nn += __shfl_xor_sync(0xffffffffu, nn, o);
#pragma unroll
                for (int r = 0; r < R; r++) d[r] += __shfl_xor_sync(0xffffffffu, d[r], o);
            }
            if (lane16 == 0) {
                float mn = sqrtf(nn);
#pragma unroll
                for (int r = 0; r < R; r++)
                    g_cr[b][r][a] = s_beta[r] * d[r] / (s_kn[r] * mn + 1e-6f);
            }
        }
    }
    __syncthreads();   // part1/alloc reads done before pack overwrites scratch

    // --- pack table ---
    for (int a = tid; a < A; a += 512) {
        float w = s_ww[a];
#pragma unroll
        for (int r = 0; r < R; r++) {
            float rw = rw_prev[(b * R + r) * A + a];
            s_pack[swz(a * 4 + r)] = pack2(rw, w * rw);
        }
    }
    __syncthreads();

    const float* Lp = link_prev + (size_t)b * A * A;

    // --- phase A: column partials (u,v); thread owns 2 cols, full 128 rows ---
    {
        int col2 = 2 * tid;
        double uv0[R], uv1[R];
#pragma unroll
        for (int r = 0; r < R; r++) { uv0[r] = 0.0; uv1[r] = 0.0; }
#pragma unroll 4
        for (int j = 0; j < 128; j++) {
            int row = jbase + j;
            float2 val = *reinterpret_cast<const float2*>(Lp + (size_t)row * A + col2);
            int j4 = row * 4;
            double2 pk01 = *reinterpret_cast<const double2*>(&s_pack[swz(j4)]);
            double2 pk23 = *reinterpret_cast<const double2*>(&s_pack[swz(j4 + 2)]);
            double sx = splat2(val.x), sy = splat2(val.y);
            fma2(uv0[0], sx, pk01.x); fma2(uv0[1], sx, pk01.y);
            fma2(uv0[2], sx, pk23.x); fma2(uv0[3], sx, pk23.y);
            fma2(uv1[0], sy, pk01.x); fma2(uv1[1], sy, pk01.y);
            fma2(uv1[2], sy, pk23.x); fma2(uv1[3], sy, pk23.y);
        }
#pragma unroll
        for (int r = 0; r < R; r++) {
            double2 st; st.x = uv0[r]; st.y = uv1[r];
            *reinterpret_cast<double2*>(&g_UVp[stripe][b][r][col2]) = st;
        }
    }

    // --- phase B: row dots (p,q); 4 threads per row, 256 cols each (L2-hot) ---
    {
        int rowl = tid >> 2, quarter = tid & 3;
        int row = jbase + rowl;
        int cbase = quarter * 256;
        const float* Lr = Lp + (size_t)row * A + cbase;
        double pq[R] = {0.0, 0.0, 0.0, 0.0};
#pragma unroll 4
        for (int cs = 0; cs < 64; cs++) {
            float4 val = *reinterpret_cast<const float4*>(Lr + cs * 4);
            int col4 = (cbase + cs * 4) * 4;
            {
                double2 pk01 = *reinterpret_cast<const double2*>(&s_pack[swz(col4)]);
                double2 pk23 = *reinterpret_cast<const double2*>(&s_pack[swz(col4 + 2)]);
                double s = splat2(val.x);
                fma2(pq[0], s, pk01.x); fma2(pq[1], s, pk01.y);
                fma2(pq[2], s, pk23.x); fma2(pq[3], s, pk23.y);
            }
            {
                double2 pk01 = *reinterpret_cast<const double2*>(&s_pack[swz(col4 + 4)]);
                double2 pk23 = *reinterpret_cast<const double2*>(&s_pack[swz(col4 + 6)]);
                double s = splat2(val.y);
                fma2(pq[0], s, pk01.x); fma2(pq[1], s, pk01.y);
                fma2(pq[2], s, pk23.x); fma2(pq[3], s, pk23.y);
            }
            {
                double2 pk01 = *reinterpret_cast<const double2*>(&s_pack[swz(col4 + 8)]);
                double2 pk23 = *reinterpret_cast<const double2*>(&s_pack[swz(col4 + 10)]);
                double s = splat2(val.z);
                fma2(pq[0], s, pk01.x); fma2(pq[1], s, pk01.y);
                fma2(pq[2], s, pk23.x); fma2(pq[3], s, pk23.y);
            }
            {
                double2 pk01 = *reinterpret_cast<const double2*>(&s_pack[swz(col4 + 12)]);
                double2 pk23 = *reinterpret_cast<const double2*>(&s_pack[swz(col4 + 14)]);
                double s = splat2(val.w);
                fma2(pq[0], s, pk01.x); fma2(pq[1], s, pk01.y);
                fma2(pq[2], s, pk23.x); fma2(pq[3], s, pk23.y);
            }
        }
#pragma unroll
        for (int r = 0; r < R; r++) {
            pq[r] = add2(pq[r], __shfl_xor_sync(0xffffffffu, pq[r], 1));
            pq[r] = add2(pq[r], __shfl_xor_sync(0xffffffffu, pq[r], 2));
        }
        if (quarter == 0) {
#pragma unroll
            for (int r = 0; r < R; r++) g_PQ[b][r][row] = pq[r];
        }
    }
}

// ============ K8: UV reduce + cr softmax + read weights + rv GEMV + output ====
__global__ void __launch_bounds__(512, 1)
k8_read_out(const float* __restrict__ rw_prev, const float* __restrict__ prec_prev,
            const float* __restrict__ W_rd, const float* __restrict__ b_rd,
            float* __restrict__ out) {
    int b = blockIdx.x;
    int tid = threadIdx.x;  // 512
    __shared__ float s_wr[R][A];
    __shared__ float s_racc[16][R][M];
    __shared__ float s_rv[R * M];
    __shared__ float s_out[2][O_OUT];
    __shared__ float s_pi[R][3];
    __shared__ float s_red[16];

    if (tid < R) {
        float l0 = g_iface[b][OFF_PI + tid * 3 + 0];
        float l1 = g_iface[b][OFF_PI + tid * 3 + 1];
        float l2 = g_iface[b][OFF_PI + tid * 3 + 2];
        float mx = fmaxf(l0, fmaxf(l1, l2));
        float e0 = __expf(l0 - mx), e1 = __expf(l1 - mx), e2 = __expf(l2 - mx);
        float inv = 1.f / (e0 + e1 + e2);
        s_pi[tid][0] = e0 * inv; s_pi[tid][1] = e1 * inv; s_pi[tid][2] = e2 * inv;
    }

#pragma unroll
    for (int r = 0; r < R; r++) {
        float l0 = g_cr[b][r][tid], l1 = g_cr[b][r][tid + 512];
        float mx = blockMax<512>(fmaxf(l0, l1), s_red);
        float e0 = __expf(l0 - mx), e1 = __expf(l1 - mx);
        float s = blockSum<512>(e0 + e1, s_red);
        float inv = 1.f / s;
        s_wr[r][tid] = e0 * inv;
        s_wr[r][tid + 512] = e1 * inv;
    }
    __syncthreads();

    for (int ii = 0; ii < 2; ii++) {
        int a = tid + ii * 512;
        float ww = g_ww[b][a];
        float pp = prec_prev[b * A + a];
#pragma unroll
        for (int r = 0; r < R; r++) {
            float rw = rw_prev[(b * R + r) * A + a];
            float2 PQ = unpack2(g_PQ[b][r][a]);
            double uvs = g_UVp[0][b][r][a];
#pragma unroll
            for (int s8 = 1; s8 < 8; s8++) uvs = add2(uvs, g_UVp[s8][b][r][a]);
            float2 UV = unpack2(uvs);
            float Sr = g_S[b][r], Tr = g_T[b][r];
            float fwd = (1.f - ww) * PQ.x - PQ.y + ww * (Sr - pp * rw);
            float bwd = (1.f - ww) * UV.x - UV.y + pp * (Tr - ww * rw);
            float cr = s_wr[r][a];
            s_wr[r][a] = s_pi[r][0] * bwd + s_pi[r][1] * cr + s_pi[r][2] * fwd;
        }
    }
    __syncthreads();

    {
        int w = tid >> 5, lane = tid & 31;
        float acc[2][R] = {{0, 0, 0, 0}, {0, 0, 0, 0}};
#pragma unroll 4
        for (int i = 0; i < 64; i++) {
            int a = i * 16 + w;
            float m0 = g_mem[b][a][lane];
            float m1 = g_mem[b][a][lane + 32];
#pragma unroll
            for (int r = 0; r < R; r++) {
                float wr = s_wr[r][a];
                acc[0][r] = fmaf(wr, m0, acc[0][r]);
                acc[1][r] = fmaf(wr, m1, acc[1][r]);
            }
        }
#pragma unroll
        for (int r = 0; r < R; r++) {
            s_racc[w][r][lane] = acc[0][r];
            s_racc[w][r][lane + 32] = acc[1][r];
        }
    }
    __syncthreads();
    if (tid < R * M) {
        float s = 0.f;
#pragma unroll
        for (int w = 0; w < 16; w++) s += s_racc[w][tid >> 6][tid & 63];
        s_rv[tid] = s;
    }
    __syncthreads();

    {
        int half = tid >> 8, col = tid & 255;
        float acc = 0.f;
        const float* W = W_rd + (size_t)half * 128 * O_OUT + col;
#pragma unroll 8
        for (int j = 0; j < 128; j++)
            acc = fmaf(s_rv[half * 128 + j], W[(size_t)j * O_OUT], acc);
        s_out[half][col] = acc;
    }
    __syncthreads();
    if (tid < O_OUT) {
        out[b * O_OUT + tid] = s_out[0][tid] + s_out[1][tid] + g_outhid[b][tid] + b_rd[tid];
    }
}

// ----------------- launch -----------------
extern "C" void kernel_launch(void* const* d_in, const int* in_sizes, int n_in,
                              void* d_out, int out_size) {
    (void)in_sizes; (void)n_in; (void)out_size;
    const float* x          = (const float*)d_in[0];
    const float* h_prev     = (const float*)d_in[1];
    const float* c_prev     = (const float*)d_in[2];
    const float* mem_prev   = (const float*)d_in[3];
    const float* rw_prev    = (const float*)d_in[4];
    const float* ww_prev    = (const float*)d_in[5];
    const float* usage_prev = (const float*)d_in[6];
    const float* prec_prev  = (const float*)d_in[7];
    const float* link_prev  = (const float*)d_in[8];
    const float* rv_prev    = (const float*)d_in[9];
    const float* Wx         = (const float*)d_in[10];
    const float* Wh         = (const float*)d_in[11];
    const float* b_lstm     = (const float*)d_in[12];
    const float* W_hid      = (const float*)d_in[13];
    const float* b_hid      = (const float*)d_in[14];
    const float* W_if       = (const float*)d_in[15];
    const float* b_if       = (const float*)d_in[16];
    const float* W_rd       = (const float*)d_in[17];
    const float* b_rd       = (const float*)d_in[18];
    float* out = (float*)d_out;

    k1_zpart<<<dim3(4, 32), 256>>>(x, h_prev, rv_prev, Wx, Wh);
    k23_lstm_iface<<<dim3(2, B), 736>>>(c_prev, b_lstm, W_if, W_hid, b_if, b_hid);
    k4b_rank<<<dim3(8, B), 256>>>(rw_prev, ww_prev, usage_prev, mem_prev);
    k57_mem_link<<<dim3(8, B), 512>>>(mem_prev, link_prev, rw_prev, prec_prev);
    k8_read_out<<<B, 512>>>(rw_prev, prec_prev, W_rd, b_rd, out);
}

// round 12
// speedup vs baseline: 1.5991x; 1.3875x over previous
#include <cuda_runtime.h>
#include <math.h>

#define B 16
#define I_IN 256
#define H 512
#define O_OUT 256
#define A 1024
#define M 64
#define R 4
#define IFW 471
#define N4H 2048
#define NCOLS3 (IFW + O_OUT)   // 727

// interface offsets
#define OFF_KR     0
#define OFF_BETAR  256
#define OFF_KW     260
#define OFF_BETAW  324
#define OFF_ERASE  325
#define OFF_WRITEV 389
#define OFF_FREE   453
#define OFF_GA     457
#define OFF_GW     458
#define OFF_PI     459

// skewed pack index: groups of 16 doubles padded to 18 (bank-conflict-free
// for lane-stride-128B access patterns: stride 144 B -> bank 4l mod 32)
#define PACKN (18 * 256)
__device__ __forceinline__ int packIdx(int a) { return 18 * (a >> 2) + 4 * (a & 3); }

// ----------------- device scratch -----------------
__device__ float  g_zpart[32][B][N4H];
__device__ float  g_iface[B][IFW];
__device__ float  g_outhid[B][O_OUT];
__device__ float  g_usage[B][A];
__device__ int    g_rank[B][A];
__device__ float  g_cwlog[B][A];
__device__ float  g_ww[B][A];
__device__ float  g_S[B][R];
__device__ float  g_T[B][R];
__device__ float  g_mem[B][A][M];
__device__ float  g_cr[B][R][A];
__device__ double g_PQ[B][R][A];        // packed (p,q)
__device__ double g_UVp[8][B][R][A];    // packed (u,v) partials per stripe

__device__ __forceinline__ float sigf(float x) { return 1.f / (1.f + __expf(-x)); }
__device__ __forceinline__ float oneplusf(float x) {
    return 1.f + (x > 20.f ? x : log1pf(__expf(x)));
}

// packed f32x2 helpers (double as bit-carrier)
__device__ __forceinline__ double pack2(float lo, float hi) {
    double d; asm("mov.b64 %0, {%1,%2};" : "=d"(d) : "f"(lo), "f"(hi)); return d;
}
__device__ __forceinline__ double splat2(float v) {
    double d; asm("mov.b64 %0, {%1,%1};" : "=d"(d) : "f"(v)); return d;
}
__device__ __forceinline__ void fma2(double& acc, double a, double b) {
    asm("fma.rn.f32x2 %0, %1, %2, %3;" : "=d"(acc) : "d"(a), "d"(b), "d"(acc));
}
__device__ __forceinline__ double add2(double a, double b) {
    double d; asm("add.rn.f32x2 %0, %1, %2;" : "=d"(d) : "d"(a), "d"(b)); return d;
}
__device__ __forceinline__ float2 unpack2(double d) {
    float2 f;
    asm("mov.b64 {%0,%1}, %2;" : "=f"(f.x), "=f"(f.y) : "l"(__double_as_longlong(d)));
    return f;
}

template <int NT>
__device__ __forceinline__ float blockSum(float v, float* s_red) {
    int lane = threadIdx.x & 31, w = threadIdx.x >> 5;
#pragma unroll
    for (int o = 16; o; o >>= 1) v += __shfl_down_sync(0xffffffffu, v, o);
    if (lane == 0) s_red[w] = v;
    __syncthreads();
    if (w == 0) {
        float x = (lane < NT / 32) ? s_red[lane] : 0.f;
#pragma unroll
        for (int o = 16; o; o >>= 1) x += __shfl_down_sync(0xffffffffu, x, o);
        if (lane == 0) s_red[0] = x;
    }
    __syncthreads();
    float res = s_red[0];
    __syncthreads();
    return res;
}
template <int NT>
__device__ __forceinline__ float blockMax(float v, float* s_red) {
    int lane = threadIdx.x & 31, w = threadIdx.x >> 5;
#pragma unroll
    for (int o = 16; o; o >>= 1) v = fmaxf(v, __shfl_down_sync(0xffffffffu, v, o));
    if (lane == 0) s_red[w] = v;
    __syncthreads();
    if (w == 0) {
        float x = (lane < NT / 32) ? s_red[lane] : -1e30f;
#pragma unroll
        for (int o = 16; o; o >>= 1) x = fmaxf(x, __shfl_down_sync(0xffffffffu, x, o));
        if (lane == 0) s_red[0] = x;
    }
    __syncthreads();
    float res = s_red[0];
    __syncthreads();
    return res;
}

// ============ K1: z GEMM, k-split 32 chunks of 32, packed f32x2 (128 blocks) ============
__global__ void __launch_bounds__(256, 1)
k1_zpart(const float* __restrict__ x, const float* __restrict__ h_prev,
         const float* __restrict__ rv_prev, const float* __restrict__ Wx,
         const float* __restrict__ Wh) {
    __shared__ double s_in2[B][32];
    int tid = threadIdx.x;
    int ntile = blockIdx.x;
    int kc = blockIdx.y;
    int kbase = kc * 32;
    for (int idx = tid; idx < B * 32; idx += 256) {
        int b = idx >> 5, kl = idx & 31;
        int kk = kbase + kl;
        float v;
        if (kk < 256) v = x[b * I_IN + kk];
        else if (kk < 512) v = rv_prev[b * 256 + (kk - 256)];
        else v = h_prev[b * H + (kk - 512)];
        s_in2[b][kl] = splat2(v);
    }
    __syncthreads();
    int n0 = ntile * 512 + tid * 2;
    const float* Wbase = (kbase < 512) ? (Wx + (size_t)kbase * N4H)
                                       : (Wh + (size_t)(kbase - 512) * N4H);
    const char* Wp = (const char*)(Wbase + n0);
    double acc2[B];
#pragma unroll
    for (int b = 0; b < B; b++) acc2[b] = 0.0;
#pragma unroll 4
    for (int kl = 0; kl < 32; kl++) {
        double w2 = *(const double*)(Wp + (size_t)kl * (N4H * 4));
#pragma unroll
        for (int b = 0; b < B; b++) fma2(acc2[b], s_in2[b][kl], w2);
    }
#pragma unroll
    for (int b = 0; b < B; b++)
        *(double*)&g_zpart[kc][b][n0] = acc2[b];
}

// ============ K23: LSTM (z reduce) + iface/out_hidden GEMM, grid (2, B) ============
__global__ void __launch_bounds__(736, 1)
k23_lstm_iface(const float* __restrict__ c_prev, const float* __restrict__ b_lstm,
               const float* __restrict__ W_if, const float* __restrict__ W_hid,
               const float* __restrict__ b_if, const float* __restrict__ b_hid) {
    __shared__ float s_h[H];
    int tid = threadIdx.x;
    int half = blockIdx.x;
    int b = blockIdx.y;

    if (tid < H) {
        float zv[4];
#pragma unroll
        for (int g = 0; g < 4; g++) {
            int n = g * H + tid;
            float s = b_lstm[n];
#pragma unroll
            for (int kc = 0; kc < 32; kc++) s += g_zpart[kc][b][n];
            zv[g] = s;
        }
        float c = sigf(zv[1]) * c_prev[b * H + tid] + sigf(zv[0]) * tanhf(zv[2]);
        s_h[tid] = sigf(zv[3]) * tanhf(c);
    }
    __syncthreads();

    int col = half * 368 + tid;
    if (tid < 368 && col < NCOLS3) {
        float a0 = 0.f, a1 = 0.f, a2 = 0.f, a3 = 0.f;
        if (col < IFW) {
            const float* W = W_if + col;
#pragma unroll 4
            for (int k = 0; k < H; k += 4) {
                a0 = fmaf(s_h[k],     W[(size_t)(k)     * IFW], a0);
                a1 = fmaf(s_h[k + 1], W[(size_t)(k + 1) * IFW], a1);
                a2 = fmaf(s_h[k + 2], W[(size_t)(k + 2) * IFW], a2);
                a3 = fmaf(s_h[k + 3], W[(size_t)(k + 3) * IFW], a3);
            }
            g_iface[b][col] = (a0 + a1) + (a2 + a3) + b_if[col];
        } else {
            int c2 = col - IFW;
            const float* W = W_hid + c2;
#pragma unroll 4
            for (int k = 0; k < H; k += 4) {
                a0 = fmaf(s_h[k],     W[(size_t)(k)     * O_OUT], a0);
                a1 = fmaf(s_h[k + 1], W[(size_t)(k + 1) * O_OUT], a1);
                a2 = fmaf(s_h[k + 2], W[(size_t)(k + 2) * O_OUT], a2);
                a3 = fmaf(s_h[k + 3], W[(size_t)(k + 3) * O_OUT], a3);
            }
            g_outhid[b][c2] = (a0 + a1) + (a2 + a3) + b_hid[c2];
        }
    }
}

// ============ K4b: usage (in-block) + rank (broadcast scan) + cwlog ============
__global__ void __launch_bounds__(256, 1)
k4b_rank(const float* __restrict__ rw_prev, const float* __restrict__ ww_prev,
         const float* __restrict__ usage_prev, const float* __restrict__ mem_prev) {
    __shared__ float s_u[A];
    __shared__ float s_kw[M];
    __shared__ float s_free[R];
    __shared__ float s_bw[1];
    int tid = threadIdx.x;
    int chunk = blockIdx.x, b = blockIdx.y;

    if (tid < R) s_free[tid] = sigf(g_iface[b][OFF_FREE + tid]);
    if (tid < M) s_kw[tid] = g_iface[b][OFF_KW + tid];
    if (tid == 0) s_bw[0] = oneplusf(g_iface[b][OFF_BETAW]);
    __syncthreads();

#pragma unroll
    for (int ii = 0; ii < 4; ii++) {
        int a = tid + ii * 256;
        float psi = 1.f;
#pragma unroll
        for (int r = 0; r < R; r++)
            psi *= (1.f - s_free[r] * rw_prev[(b * R + r) * A + a]);
        float u = usage_prev[b * A + a], w = ww_prev[b * A + a];
        s_u[a] = (u + w - u * w) * psi;
    }
    __syncthreads();
    if (tid < 128) g_usage[b][chunk * 128 + tid] = s_u[chunk * 128 + tid];

    {
        int slot = chunk * 128 + (tid >> 1);
        int half = tid & 1;
        float u = s_u[slot];
        int cnt = 0;
        int base = half * 512;
#pragma unroll 8
        for (int i = 0; i < 512; i++) {
            float v = s_u[base + i];
            int ia = base + i;
            cnt += (v < u) || (v == u && ia < slot);
        }
        cnt += __shfl_xor_sync(0xffffffffu, cnt, 1);
        if (half == 0) g_rank[b][slot] = cnt;
    }

    {
        int row = chunk * 128 + (tid >> 1);
        int half = tid & 1;
        const float4* mrow =
            reinterpret_cast<const float4*>(mem_prev + ((size_t)(b * A + row)) * M) + half * 8;
        float d = 0.f, n = 0.f;
#pragma unroll
        for (int q = 0; q < 8; q++) {
            float4 v = mrow[q];
            int m0 = half * 32 + q * 4;
            d += v.x * s_kw[m0] + v.y * s_kw[m0 + 1] + v.z * s_kw[m0 + 2] + v.w * s_kw[m0 + 3];
            n += v.x * v.x + v.y * v.y + v.z * v.z + v.w * v.w;
        }
        d += __shfl_xor_sync(0xffffffffu, d, 1);
        n += __shfl_xor_sync(0xffffffffu, n, 1);
        if (half == 0) {
            float kn2 = 0.f;
#pragma unroll
            for (int m = 0; m < M; m++) { float v = s_kw[m]; kn2 = fmaf(v, v, kn2); }
            g_cwlog[b][row] = s_bw[0] * d / (sqrtf(kn2) * sqrtf(n) + 1e-6f);
        }
    }
}

// ============ K57: alloc/ww (inline) + mem write + c_r + link pass (wf-coalesced) ====
__global__ void __launch_bounds__(512, 1)
k57_mem_link(const float* __restrict__ mem_prev, const float* __restrict__ link_prev,
             const float* __restrict__ rw_prev, const float* __restrict__ prec_prev) {
    __shared__ double s_pack[PACKN];          // 36 KB skewed; front overlaid by cumprod scratch
    __shared__ float  s_ww[A];
    __shared__ float  s_kr[R][M];
    __shared__ float  s_er[M], s_wv[M];
    __shared__ float  s_beta[R], s_kn[R];
    __shared__ float  s_red[16];
    int tid = threadIdx.x;                    // 512
    int stripe = blockIdx.x;                  // 8 stripes of 128 rows
    int b = blockIdx.y;
    int jbase = stripe * 128;

    float* s_sorted = (float*)s_pack;         // [A]
    float* s_tmp = ((float*)s_pack) + A;      // [A]

    // --- params ---
    if (tid < 256) {
        int r = tid >> 6, m = tid & 63;
        s_kr[r][m] = g_iface[b][OFF_KR + r * M + m];
    } else if (tid < 256 + M) {
        s_er[tid - 256] = sigf(g_iface[b][OFF_ERASE + (tid - 256)]);
    } else if (tid < 256 + 2 * M) {
        s_wv[tid - 256 - M] = g_iface[b][OFF_WRITEV + (tid - 256 - M)];
    }
    __syncthreads();
    if (tid < R) {
        s_beta[tid] = oneplusf(g_iface[b][OFF_BETAR + tid]);
        float s = 0.f;
#pragma unroll
        for (int m = 0; m < M; m++) { float v = s_kr[tid][m]; s = fmaf(v, v, s); }
        s_kn[tid] = sqrtf(s);
    }

    // --- alloc + ww (redundant per block) ---
    float u0 = g_usage[b][tid], u1 = g_usage[b][tid + 512];
    int r0 = g_rank[b][tid], r1 = g_rank[b][tid + 512];
    s_sorted[r0] = u0;
    s_sorted[r1] = u1;
    __syncthreads();
    {
        float* src = s_sorted;
        float* dst = s_tmp;
        for (int off = 1; off < A; off <<= 1) {
            for (int i = tid; i < A; i += 512)
                dst[i] = (i >= off) ? src[i - off] * src[i] : src[i];
            __syncthreads();
            float* t = src; src = dst; dst = t;
        }
        float alloc0 = (1.f - u0) * (r0 == 0 ? 1.f : src[r0 - 1]);
        float alloc1 = (1.f - u1) * (r1 == 0 ? 1.f : src[r1 - 1]);

        float l0 = g_cwlog[b][tid], l1 = g_cwlog[b][tid + 512];
        float mx = blockMax<512>(fmaxf(l0, l1), s_red);
        float e0 = __expf(l0 - mx), e1 = __expf(l1 - mx);
        float ssum = blockSum<512>(e0 + e1, s_red);
        float inv = 1.f / ssum;

        float ga = sigf(g_iface[b][OFF_GA]), gw = sigf(g_iface[b][OFF_GW]);
        float wwv0 = gw * (ga * alloc0 + (1.f - ga) * e0 * inv);
        float wwv1 = gw * (ga * alloc1 + (1.f - ga) * e1 * inv);
        s_ww[tid] = wwv0;
        s_ww[tid + 512] = wwv1;

        if (stripe == 0) {
            g_ww[b][tid] = wwv0;
            g_ww[b][tid + 512] = wwv1;
            float pp0 = prec_prev[b * A + tid], pp1 = prec_prev[b * A + tid + 512];
            float sS[R], sT[R];
#pragma unroll
            for (int r = 0; r < R; r++) {
                float rw0 = rw_prev[(b * R + r) * A + tid];
                float rw1 = rw_prev[(b * R + r) * A + tid + 512];
                sS[r] = fmaf(pp0, rw0, pp1 * rw1);
                sT[r] = fmaf(wwv0, rw0, wwv1 * rw1);
            }
#pragma unroll
            for (int r = 0; r < R; r++) {
                float v = blockSum<512>(sS[r], s_red);
                if (tid == 0) g_S[b][r] = v;
                v = blockSum<512>(sT[r], s_red);
                if (tid == 0) g_T[b][r] = v;
            }
        }
    }
    __syncthreads();

    // --- part 1: mem update + cr logits for rows [jbase, jbase+128) ---
    {
        int lane16 = tid & 15, m0 = lane16 * 4;
#pragma unroll
        for (int pass = 0; pass < 4; pass++) {
            int a = jbase + pass * 32 + (tid >> 4);
            float w = s_ww[a];
            float4 v = *reinterpret_cast<const float4*>(mem_prev + ((size_t)(b * A + a)) * M + m0);
            float n0 = v.x * (1.f - w * s_er[m0])     + w * s_wv[m0];
            float n1 = v.y * (1.f - w * s_er[m0 + 1]) + w * s_wv[m0 + 1];
            float n2 = v.z * (1.f - w * s_er[m0 + 2]) + w * s_wv[m0 + 2];
            float n3 = v.w * (1.f - w * s_er[m0 + 3]) + w * s_wv[m0 + 3];
            *reinterpret_cast<float4*>(&g_mem[b][a][m0]) = make_float4(n0, n1, n2, n3);
            float nn = n0 * n0 + n1 * n1 + n2 * n2 + n3 * n3;
            float d[R];
#pragma unroll
            for (int r = 0; r < R; r++)
                d[r] = n0 * s_kr[r][m0] + n1 * s_kr[r][m0 + 1] +
                       n2 * s_kr[r][m0 + 2] + n3 * s_kr[r][m0 + 3];
#pragma unroll
            for (int o = 8; o; o >>= 1) {
                nn += __shfl_xor_sync(0xffffffffu, nn, o);
#pragma unroll
                for (int r = 0; r < R; r++) d[r] += __shfl_xor_sync(0xffffffffu, d[r], o);
            }
            if (lane16 == 0) {
                float mn = sqrtf(nn);
#pragma unroll
                for (int r = 0; r < R; r++)
                    g_cr[b][r][a] = s_beta[r] * d[r] / (s_kn[r] * mn + 1e-6f);
            }
        }
    }
    __syncthreads();   // alloc/part1 reads done before pack overwrites scratch

    // --- pack table (skewed layout) ---
    for (int a = tid; a < A; a += 512) {
        float w = s_ww[a];
        double* dst = s_pack + packIdx(a);
#pragma unroll
        for (int r = 0; r < R; r++) {
            float rw = rw_prev[(b * R + r) * A + a];
            dst[r] = pack2(rw, w * rw);
        }
    }
    __syncthreads();

    const float* Lp = link_prev + (size_t)b * A * A;

    // --- phase A: column partials (u,v); thread owns 2 cols, full 128 rows ---
    {
        int col2 = 2 * tid;
        double uv0[R], uv1[R];
#pragma unroll
        for (int r = 0; r < R; r++) { uv0[r] = 0.0; uv1[r] = 0.0; }
#pragma unroll 4
        for (int j = 0; j < 128; j++) {
            int row = jbase + j;
            float2 val = *reinterpret_cast<const float2*>(Lp + (size_t)row * A + col2);
            const double* base = s_pack + packIdx(row);
            double2 pk01 = *reinterpret_cast<const double2*>(base);
            double2 pk23 = *reinterpret_cast<const double2*>(base + 2);
            double sx = splat2(val.x), sy = splat2(val.y);
            fma2(uv0[0], sx, pk01.x); fma2(uv0[1], sx, pk01.y);
            fma2(uv0[2], sx, pk23.x); fma2(uv0[3], sx, pk23.y);
            fma2(uv1[0], sy, pk01.x); fma2(uv1[1], sy, pk01.y);
            fma2(uv1[2], sy, pk23.x); fma2(uv1[3], sy, pk23.y);
        }
#pragma unroll
        for (int r = 0; r < R; r++) {
            double2 st; st.x = uv0[r]; st.y = uv1[r];
            *reinterpret_cast<double2*>(&g_UVp[stripe][b][r][col2]) = st;
        }
    }

    // --- phase B: row dots (p,q); warp-coherent, 2 rows/thread, skewed pack ---
    {
        int lane8 = tid & 7;
        int rowg = tid >> 3;               // 0..63
        int row0 = jbase + rowg;
        int row1 = jbase + rowg + 64;
        const float* Lr0 = Lp + (size_t)row0 * A;
        const float* Lr1 = Lp + (size_t)row1 * A;
        double pq0[R] = {0.0, 0.0, 0.0, 0.0};
        double pq1[R] = {0.0, 0.0, 0.0, 0.0};
#pragma unroll 2
        for (int step = 0; step < 32; step++) {
            int col = step * 32 + lane8 * 4;
            float4 v0 = *reinterpret_cast<const float4*>(Lr0 + col);
            float4 v1 = *reinterpret_cast<const float4*>(Lr1 + col);
            const double* base = s_pack + 18 * (col >> 2);
            double2 p0 = *reinterpret_cast<const double2*>(base + 0);
            double2 p1 = *reinterpret_cast<const double2*>(base + 2);
            double2 p2 = *reinterpret_cast<const double2*>(base + 4);
            double2 p3 = *reinterpret_cast<const double2*>(base + 6);
            double2 p4 = *reinterpret_cast<const double2*>(base + 8);
            double2 p5 = *reinterpret_cast<const double2*>(base + 10);
            double2 p6 = *reinterpret_cast<const double2*>(base + 12);
            double2 p7 = *reinterpret_cast<const double2*>(base + 14);
            double s;
            s = splat2(v0.x); fma2(pq0[0], s, p0.x); fma2(pq0[1], s, p0.y);
                              fma2(pq0[2], s, p1.x); fma2(pq0[3], s, p1.y);
            s = splat2(v0.y); fma2(pq0[0], s, p2.x); fma2(pq0[1], s, p2.y);
                              fma2(pq0[2], s, p3.x); fma2(pq0[3], s, p3.y);
            s = splat2(v0.z); fma2(pq0[0], s, p4.x); fma2(pq0[1], s, p4.y);
                              fma2(pq0[2], s, p5.x); fma2(pq0[3], s, p5.y);
            s = splat2(v0.w); fma2(pq0[0], s, p6.x); fma2(pq0[1], s, p6.y);
                              fma2(pq0[2], s, p7.x); fma2(pq0[3], s, p7.y);
            s = splat2(v1.x); fma2(pq1[0], s, p0.x); fma2(pq1[1], s, p0.y);
                              fma2(pq1[2], s, p1.x); fma2(pq1[3], s, p1.y);
            s = splat2(v1.y); fma2(pq1[0], s, p2.x); fma2(pq1[1], s, p2.y);
                              fma2(pq1[2], s, p3.x); fma2(pq1[3], s, p3.y);
            s = splat2(v1.z); fma2(pq1[0], s, p4.x); fma2(pq1[1], s, p4.y);
                              fma2(pq1[2], s, p5.x); fma2(pq1[3], s, p5.y);
            s = splat2(v1.w); fma2(pq1[0], s, p6.x); fma2(pq1[1], s, p6.y);
                              fma2(pq1[2], s, p7.x); fma2(pq1[3], s, p7.y);
        }
#pragma unroll
        for (int r = 0; r < R; r++) {
            pq0[r] = add2(pq0[r], __shfl_xor_sync(0xffffffffu, pq0[r], 1));
            pq0[r] = add2(pq0[r], __shfl_xor_sync(0xffffffffu, pq0[r], 2));
            pq0[r] = add2(pq0[r], __shfl_xor_sync(0xffffffffu, pq0[r], 4));
            pq1[r] = add2(pq1[r], __shfl_xor_sync(0xffffffffu, pq1[r], 1));
            pq1[r] = add2(pq1[r], __shfl_xor_sync(0xffffffffu, pq1[r], 2));
            pq1[r] = add2(pq1[r], __shfl_xor_sync(0xffffffffu, pq1[r], 4));
        }
        if (lane8 == 0) {
#pragma unroll
            for (int r = 0; r < R; r++) {
                g_PQ[b][r][row0] = pq0[r];
                g_PQ[b][r][row1] = pq1[r];
            }
        }
    }
}

// ============ K8: UV reduce + cr softmax + read weights + rv GEMV + output ====
__global__ void __launch_bounds__(512, 1)
k8_read_out(const float* __restrict__ rw_prev, const float* __restrict__ prec_prev,
            const float* __restrict__ W_rd, const float* __restrict__ b_rd,
            float* __restrict__ out) {
    int b = blockIdx.x;
    int tid = threadIdx.x;  // 512
    __shared__ float s_wr[R][A];
    __shared__ float s_racc[16][R][M];
    __shared__ float s_rv[R * M];
    __shared__ float s_out[2][O_OUT];
    __shared__ float s_pi[R][3];
    __shared__ float s_red[16];

    if (tid < R) {
        float l0 = g_iface[b][OFF_PI + tid * 3 + 0];
        float l1 = g_iface[b][OFF_PI + tid * 3 + 1];
        float l2 = g_iface[b][OFF_PI + tid * 3 + 2];
        float mx = fmaxf(l0, fmaxf(l1, l2));
        float e0 = __expf(l0 - mx), e1 = __expf(l1 - mx), e2 = __expf(l2 - mx);
        float inv = 1.f / (e0 + e1 + e2);
        s_pi[tid][0] = e0 * inv; s_pi[tid][1] = e1 * inv; s_pi[tid][2] = e2 * inv;
    }

#pragma unroll
    for (int r = 0; r < R; r++) {
        float l0 = g_cr[b][r][tid], l1 = g_cr[b][r][tid + 512];
        float mx = blockMax<512>(fmaxf(l0, l1), s_red);
        float e0 = __expf(l0 - mx), e1 = __expf(l1 - mx);
        float s = blockSum<512>(e0 + e1, s_red);
        float inv = 1.f / s;
        s_wr[r][tid] = e0 * inv;
        s_wr[r][tid + 512] = e1 * inv;
    }
    __syncthreads();

    for (int ii = 0; ii < 2; ii++) {
        int a = tid + ii * 512;
        float ww = g_ww[b][a];
        float pp = prec_prev[b * A + a];
#pragma unroll
        for (int r = 0; r < R; r++) {
            float rw = rw_prev[(b * R + r) * A + a];
            float2 PQ = unpack2(g_PQ[b][r][a]);
            double uvs = g_UVp[0][b][r][a];
#pragma unroll
            for (int s8 = 1; s8 < 8; s8++) uvs = add2(uvs, g_UVp[s8][b][r][a]);
            float2 UV = unpack2(uvs);
            float Sr = g_S[b][r], Tr = g_T[b][r];
            float fwd = (1.f - ww) * PQ.x - PQ.y + ww * (Sr - pp * rw);
            float bwd = (1.f - ww) * UV.x - UV.y + pp * (Tr - ww * rw);
            float cr = s_wr[r][a];
            s_wr[r][a] = s_pi[r][0] * bwd + s_pi[r][1] * cr + s_pi[r][2] * fwd;
        }
    }
    __syncthreads();

    {
        int w = tid >> 5, lane = tid & 31;
        float acc[2][R] = {{0, 0, 0, 0}, {0, 0, 0, 0}};
#pragma unroll 4
        for (int i = 0; i < 64; i++) {
            int a = i * 16 + w;
            float m0 = g_mem[b][a][lane];
            float m1 = g_mem[b][a][lane + 32];
#pragma unroll
            for (int r = 0; r < R; r++) {
                float wr = s_wr[r][a];
                acc[0][r] = fmaf(wr, m0, acc[0][r]);
                acc[1][r] = fmaf(wr, m1, acc[1][r]);
            }
        }
#pragma unroll
        for (int r = 0; r < R; r++) {
            s_racc[w][r][lane] = acc[0][r];
            s_racc[w][r][lane + 32] = acc[1][r];
        }
    }
    __syncthreads();
    if (tid < R * M) {
        float s = 0.f;
#pragma unroll
        for (int w = 0; w < 16; w++) s += s_racc[w][tid >> 6][tid & 63];
        s_rv[tid] = s;
    }
    __syncthreads();

    {
        int half = tid >> 8, col = tid & 255;
        float acc = 0.f;
        const float* W = W_rd + (size_t)half * 128 * O_OUT + col;
#pragma unroll 8
        for (int j = 0; j < 128; j++)
            acc = fmaf(s_rv[half * 128 + j], W[(size_t)j * O_OUT], acc);
        s_out[half][col] = acc;
    }
    __syncthreads();
    if (tid < O_OUT) {
        out[b * O_OUT + tid] = s_out[0][tid] + s_out[1][tid] + g_outhid[b][tid] + b_rd[tid];
    }
}

// ----------------- launch -----------------
extern "C" void kernel_launch(void* const* d_in, const int* in_sizes, int n_in,
                              void* d_out, int out_size) {
    (void)in_sizes; (void)n_in; (void)out_size;
    const float* x          = (const float*)d_in[0];
    const float* h_prev     = (const float*)d_in[1];
    const float* c_prev     = (const float*)d_in[2];
    const float* mem_prev   = (const float*)d_in[3];
    const float* rw_prev    = (const float*)d_in[4];
    const float* ww_prev    = (const float*)d_in[5];
    const float* usage_prev = (const float*)d_in[6];
    const float* prec_prev  = (const float*)d_in[7];
    const float* link_prev  = (const float*)d_in[8];
    const float* rv_prev    = (const float*)d_in[9];
    const float* Wx         = (const float*)d_in[10];
    const float* Wh         = (const float*)d_in[11];
    const float* b_lstm     = (const float*)d_in[12];
    const float* W_hid      = (const float*)d_in[13];
    const float* b_hid      = (const float*)d_in[14];
    const float* W_if       = (const float*)d_in[15];
    const float* b_if       = (const float*)d_in[16];
    const float* W_rd       = (const float*)d_in[17];
    const float* b_rd       = (const float*)d_in[18];
    float* out = (float*)d_out;

    k1_zpart<<<dim3(4, 32), 256>>>(x, h_prev, rv_prev, Wx, Wh);
    k23_lstm_iface<<<dim3(2, B), 736>>>(c_prev, b_lstm, W_if, W_hid, b_if, b_hid);
    k4b_rank<<<dim3(8, B), 256>>>(rw_prev, ww_prev, usage_prev, mem_prev);
    k57_mem_link<<<dim3(8, B), 512>>>(mem_prev, link_prev, rw_prev, prec_prev);
    k8_read_out<<<B, 512>>>(rw_prev, prec_prev, W_rd, b_rd, out);
}